// round 8
// baseline (speedup 1.0000x reference)
#include <cuda_runtime.h>
#include <cuda_bf16.h>
#include <math.h>

#define N   4096
#define D   128
#define H   2
#define DH  64
#define FF  256
#define NE  2048
#define NNZ 65536
#define EPS 1e-5f

typedef unsigned long long u64;

// ---------------- packed f32x2 helpers ----------------
__device__ __forceinline__ u64 pack2(float lo, float hi) {
    u64 r; asm("mov.b64 %0, {%1, %2};" : "=l"(r) : "f"(lo), "f"(hi)); return r;
}
__device__ __forceinline__ void unpack2(u64 p, float& lo, float& hi) {
    asm("mov.b64 {%0, %1}, %2;" : "=f"(lo), "=f"(hi) : "l"(p));
}
__device__ __forceinline__ void fma2(u64& d, u64 a, u64 b) {
    asm("fma.rn.f32x2 %0, %1, %2, %0;" : "+l"(d) : "l"(a), "l"(b));
}
__device__ __forceinline__ void mul2(u64& d, u64 a) {
    asm("mul.rn.f32x2 %0, %0, %1;" : "+l"(d) : "l"(a));
}

// ---------------- scratch (no allocation allowed) ----------------
__device__ float g_h[N * D];
__device__ float g_q[N * D];
__device__ float g_k[N * D];
__device__ float g_v[N * D];
__device__ float g_o[N * D];
__device__ float g_t[N * D];
__device__ float g_z[N * FF];
__device__ float g_e[NE * D];
__device__ float g_bdeg[NE];
__device__ float g_ddeg[N];
__device__ int   g_edge_is64;

// ---------------- edge dtype detection ----------------
__global__ void detect_edge_kernel(const int* __restrict__ e32)
{
    if (threadIdx.x == 0 && blockIdx.x == 0) {
        int is64 = 1;
        #pragma unroll
        for (int i = 1; i < 64; i += 2)
            if (e32[i] != 0) is64 = 0;
        g_edge_is64 = is64;
    }
}

__device__ __forceinline__ int2 load_edge(const void* __restrict__ edge, int nz)
{
    if (g_edge_is64) {
        const long long* e = (const long long*)edge;
        return make_int2((int)e[nz], (int)e[NNZ + nz]);
    } else {
        const int* e = (const int*)edge;
        return make_int2(e[nz], e[NNZ + nz]);
    }
}

// ------- tiled SGEMM core: 64x64 tile, KC=32, 512 threads, reg double-buffer -------
#define APAD 68
struct GemmSmem { float As[32 * APAD]; float Bs[32 * 64]; };

__device__ __forceinline__ void gemm_tile(const float* __restrict__ A,
                                          const float* __restrict__ B,
                                          const float* __restrict__ bias,
                                          float* __restrict__ C,
                                          int Nc, int K, int act,
                                          int row0, int col0, GemmSmem& sm)
{
    int tid = threadIdx.x;            // 512 threads
    int tx = tid & 15, ty = tid >> 4; // 16 x 32

    float a_reg[4], b_reg[4];
    #pragma unroll
    for (int i = 0; i < 4; i++) {
        int ia = tid + i * 512;
        int m = ia >> 5, kk = ia & 31;
        a_reg[i] = A[(size_t)(row0 + m) * K + kk];
        int kb = ia >> 6, n = ia & 63;
        b_reg[i] = B[(size_t)kb * Nc + col0 + n];
    }

    u64 acc2[2][2] = {};
    for (int k0 = 0; k0 < K; k0 += 32) {
        __syncthreads();
        #pragma unroll
        for (int i = 0; i < 4; i++) {
            int ia = tid + i * 512;
            int m = ia >> 5, kk = ia & 31;
            sm.As[kk * APAD + m] = a_reg[i];
            int kb = ia >> 6, n = ia & 63;
            sm.Bs[kb * 64 + n] = b_reg[i];
        }
        __syncthreads();
        if (k0 + 32 < K) {
            #pragma unroll
            for (int i = 0; i < 4; i++) {
                int ia = tid + i * 512;
                int m = ia >> 5, kk = ia & 31;
                a_reg[i] = A[(size_t)(row0 + m) * K + (k0 + 32) + kk];
                int kb = ia >> 6, n = ia & 63;
                b_reg[i] = B[(size_t)(k0 + 32 + kb) * Nc + col0 + n];
            }
        }
        #pragma unroll
        for (int kk = 0; kk < 32; kk++) {
            float2 a2 = *(const float2*)&sm.As[kk * APAD + ty * 2];
            float4 b4 = *(const float4*)&sm.Bs[kk * 64 + tx * 4];
            u64 b01 = pack2(b4.x, b4.y), b23 = pack2(b4.z, b4.w);
            u64 a0 = pack2(a2.x, a2.x), a1 = pack2(a2.y, a2.y);
            fma2(acc2[0][0], a0, b01); fma2(acc2[0][1], a0, b23);
            fma2(acc2[1][0], a1, b01); fma2(acc2[1][1], a1, b23);
        }
    }
    #pragma unroll
    for (int i = 0; i < 2; i++) {
        int r = row0 + ty * 2 + i;
        float vv[4];
        unpack2(acc2[i][0], vv[0], vv[1]);
        unpack2(acc2[i][1], vv[2], vv[3]);
        #pragma unroll
        for (int j = 0; j < 4; j++) {
            int c = col0 + tx * 4 + j;
            float val = vv[j] + (bias ? bias[c] : 0.0f);
            if (act == 1) val = 1.0f / (1.0f + __expf(-val));
            C[(size_t)r * Nc + c] = val;
        }
    }
}

__global__ void sgemm_bias_act(const float* __restrict__ A, const float* __restrict__ B,
                               const float* __restrict__ bias, float* __restrict__ C,
                               int Nc, int K, int act)
{
    __shared__ GemmSmem sm;
    gemm_tile(A, B, bias, C, Nc, K, act, blockIdx.y * 64, blockIdx.x * 64, sm);
}

// fused QKV: blockIdx.z picks which projection
__global__ void qkv_gemm(const float* __restrict__ A,
                         const float* __restrict__ Wq, const float* __restrict__ bq,
                         const float* __restrict__ Wk, const float* __restrict__ bk,
                         const float* __restrict__ Wv, const float* __restrict__ bv,
                         float* __restrict__ q, float* __restrict__ k, float* __restrict__ v)
{
    __shared__ GemmSmem sm;
    const float* B; const float* bias; float* C;
    if (blockIdx.z == 0)      { B = Wq; bias = bq; C = q; }
    else if (blockIdx.z == 1) { B = Wk; bias = bk; C = k; }
    else                      { B = Wv; bias = bv; C = v; }
    gemm_tile(A, B, bias, C, D, D, 0, blockIdx.y * 64, blockIdx.x * 64, sm);
}

// ------- flash attention: BM=BN=64, DH=64, 512 threads, reg double-buffer -------
#define QP 68
__global__ void flash_attn(const float* __restrict__ q, const float* __restrict__ k,
                           const float* __restrict__ v, float* __restrict__ o)
{
    extern __shared__ float fsm[];
    float* Qs = fsm;              // [d][r]  64 x QP
    float* Ks = Qs + 64 * QP;     // [d][c]
    float* Vs = Ks + 64 * QP;     // [j][c]
    float* Ps = Vs + 64 * QP;     // [r][j]

    int tid = threadIdx.x;            // 512
    int tx = tid & 15, ty = tid >> 4; // 16 x 32
    int qrow0 = blockIdx.x * 64;
    int hcol  = blockIdx.y * DH;

    #pragma unroll
    for (int i = 0; i < 8; i++) {
        int idx = tid + i * 512;
        int r = idx >> 6, d = idx & 63;
        Qs[d * QP + r] = q[(size_t)(qrow0 + r) * D + hcol + d];
    }

    // prefetch first K/V tile into registers
    float kreg[8], vreg[8];
    #pragma unroll
    for (int i = 0; i < 8; i++) {
        int idx = tid + i * 512;
        int c = idx >> 6, d = idx & 63;
        kreg[i] = k[(size_t)c * D + hcol + d];
        vreg[i] = v[(size_t)c * D + hcol + d];
    }

    float m_i[2], l_i[2];
    u64 o2[2][4] = {};
    #pragma unroll
    for (int i = 0; i < 2; i++) { m_i[i] = -1e30f; l_i[i] = 0.0f; }
    const float scale = 0.125f;  // 1/sqrt(64)

    for (int kb = 0; kb < N; kb += 64) {
        __syncthreads();   // previous iter done with Ks/Vs; Qs ready on iter 0
        #pragma unroll
        for (int i = 0; i < 8; i++) {
            int idx = tid + i * 512;
            int c = idx >> 6, d = idx & 63;
            Ks[d * QP + c] = kreg[i];
            Vs[c * QP + d] = vreg[i];
        }
        __syncthreads();
        if (kb + 64 < N) {
            #pragma unroll
            for (int i = 0; i < 8; i++) {
                int idx = tid + i * 512;
                int c = idx >> 6, d = idx & 63;
                kreg[i] = k[(size_t)(kb + 64 + c) * D + hcol + d];
                vreg[i] = v[(size_t)(kb + 64 + c) * D + hcol + d];
            }
        }

        // S = Q @ K^T  (2 rows x 4 cols per thread, packed along cols)
        u64 s2r[2][2] = {};
        #pragma unroll
        for (int d = 0; d < 64; d++) {
            float2 a2 = *(const float2*)&Qs[d * QP + ty * 2];
            float4 b4 = *(const float4*)&Ks[d * QP + tx * 4];
            u64 b01 = pack2(b4.x, b4.y), b23 = pack2(b4.z, b4.w);
            u64 a0 = pack2(a2.x, a2.x), a1 = pack2(a2.y, a2.y);
            fma2(s2r[0][0], a0, b01); fma2(s2r[0][1], a0, b23);
            fma2(s2r[1][0], a1, b01); fma2(s2r[1][1], a1, b23);
        }

        // online softmax (16-lane row groups share ty)
        #pragma unroll
        for (int i = 0; i < 2; i++) {
            float s0, s1, s2v, s3v;
            unpack2(s2r[i][0], s0, s1);
            unpack2(s2r[i][1], s2v, s3v);
            s0 *= scale; s1 *= scale; s2v *= scale; s3v *= scale;
            float mt = fmaxf(fmaxf(s0, s1), fmaxf(s2v, s3v));
            #pragma unroll
            for (int off = 8; off >= 1; off >>= 1)
                mt = fmaxf(mt, __shfl_xor_sync(0xffffffffu, mt, off));
            float mnew = fmaxf(m_i[i], mt);
            float p0 = __expf(s0 - mnew), p1 = __expf(s1 - mnew);
            float p2 = __expf(s2v - mnew), p3 = __expf(s3v - mnew);
            float lt = (p0 + p1) + (p2 + p3);
            #pragma unroll
            for (int off = 8; off >= 1; off >>= 1)
                lt += __shfl_xor_sync(0xffffffffu, lt, off);
            float alpha = __expf(m_i[i] - mnew);
            l_i[i] = l_i[i] * alpha + lt;
            m_i[i] = mnew;
            u64 al = pack2(alpha, alpha);
            #pragma unroll
            for (int c = 0; c < 4; c++) mul2(o2[i][c], al);
            float4 pv = make_float4(p0, p1, p2, p3);
            *(float4*)&Ps[(ty * 2 + i) * QP + tx * 4] = pv;
        }
        __syncthreads();

        // O += P @ V  (packed along j)
        #pragma unroll
        for (int j = 0; j < 64; j += 2) {
            u64 a2v[2];
            #pragma unroll
            for (int i = 0; i < 2; i++)
                a2v[i] = *(const u64*)&Ps[(ty * 2 + i) * QP + j];
            float4 bj  = *(const float4*)&Vs[j * QP + tx * 4];
            float4 bj1 = *(const float4*)&Vs[(j + 1) * QP + tx * 4];
            u64 bx = pack2(bj.x, bj1.x), by = pack2(bj.y, bj1.y);
            u64 bz = pack2(bj.z, bj1.z), bw = pack2(bj.w, bj1.w);
            #pragma unroll
            for (int i = 0; i < 2; i++) {
                fma2(o2[i][0], a2v[i], bx);
                fma2(o2[i][1], a2v[i], by);
                fma2(o2[i][2], a2v[i], bz);
                fma2(o2[i][3], a2v[i], bw);
            }
        }
    }

    #pragma unroll
    for (int i = 0; i < 2; i++) {
        float inv = 1.0f / l_i[i];
        int r = qrow0 + ty * 2 + i;
        #pragma unroll
        for (int c = 0; c < 4; c++) {
            float lo, hi;
            unpack2(o2[i][c], lo, hi);
            o[(size_t)r * D + hcol + tx * 4 + c] = (lo + hi) * inv;
        }
    }
}

// ---------------- fused residual + LayerNorm ----------------
__global__ void add_ln(const float* __restrict__ hin, const float* __restrict__ t,
                       const float* __restrict__ g, const float* __restrict__ b,
                       float* __restrict__ hout)
{
    int row = blockIdx.x, tid = threadIdx.x;  // 128 threads
    float val = hin[(size_t)row * D + tid] + t[(size_t)row * D + tid];
    float s = val, s2 = val * val;
    #pragma unroll
    for (int off = 16; off >= 1; off >>= 1) {
        s  += __shfl_xor_sync(0xffffffffu, s,  off);
        s2 += __shfl_xor_sync(0xffffffffu, s2, off);
    }
    __shared__ float red[8];
    int warp = tid >> 5, lane = tid & 31;
    if (lane == 0) { red[warp] = s; red[4 + warp] = s2; }
    __syncthreads();
    s  = red[0] + red[1] + red[2] + red[3];
    s2 = red[4] + red[5] + red[6] + red[7];
    float mean = s * (1.0f / D);
    float var  = s2 * (1.0f / D) - mean * mean;
    float inv  = rsqrtf(var + EPS);
    hout[(size_t)row * D + tid] = (val - mean) * inv * g[tid] + b[tid];
}

// ---------------- hypergraph conv pieces ----------------
__global__ void zero_kernel(float* p, int n)
{
    int i = blockIdx.x * blockDim.x + threadIdx.x;
    if (i < n) p[i] = 0.0f;
}

__global__ void degree_kernel(const void* __restrict__ edge,
                              float* __restrict__ bdeg, float* __restrict__ ddeg)
{
    int i = blockIdx.x * blockDim.x + threadIdx.x;
    if (i < NNZ) {
        int2 ne = load_edge(edge, i);
        if ((unsigned)ne.x < N && (unsigned)ne.y < NE) {
            atomicAdd(&ddeg[ne.x], 1.0f);
            atomicAdd(&bdeg[ne.y], 1.0f);
        }
    }
}

__global__ void scatter_node_to_edge(const void* __restrict__ edge,
                                     const float* __restrict__ xt, float* __restrict__ e)
{
    int i = blockIdx.x * blockDim.x + threadIdx.x;   // NNZ*32 threads
    int nz = i >> 5, lane = i & 31;
    int2 ne = load_edge(edge, nz);
    if ((unsigned)ne.x >= N || (unsigned)ne.y >= NE) return;
    float4 p = *(const float4*)&xt[(size_t)ne.x * D + lane * 4];
    float* dst = &e[(size_t)ne.y * D + lane * 4];
    atomicAdd(dst + 0, p.x);
    atomicAdd(dst + 1, p.y);
    atomicAdd(dst + 2, p.z);
    atomicAdd(dst + 3, p.w);
}

__global__ void scale_by_bdeg(float* __restrict__ e, const float* __restrict__ bdeg)
{
    int i = blockIdx.x * blockDim.x + threadIdx.x;  // over NE*D
    int row = i >> 7;
    float bd = bdeg[row];
    e[i] *= (bd > 0.0f) ? (1.0f / bd) : 0.0f;
}

__global__ void scatter_edge_to_node(const void* __restrict__ edge,
                                     const float* __restrict__ e, float* __restrict__ out)
{
    int i = blockIdx.x * blockDim.x + threadIdx.x;   // NNZ*32 threads
    int nz = i >> 5, lane = i & 31;
    int2 ne = load_edge(edge, nz);
    if ((unsigned)ne.x >= N || (unsigned)ne.y >= NE) return;
    float4 p = *(const float4*)&e[(size_t)ne.y * D + lane * 4];
    float* dst = &out[(size_t)ne.x * D + lane * 4];
    atomicAdd(dst + 0, p.x);
    atomicAdd(dst + 1, p.y);
    atomicAdd(dst + 2, p.z);
    atomicAdd(dst + 3, p.w);
}

__global__ void finalize_kernel(float* __restrict__ out, const float* __restrict__ ddeg,
                                const float* __restrict__ bh)
{
    int i = blockIdx.x * blockDim.x + threadIdx.x;  // over N*D
    int row = i >> 7, d = i & 127;
    float dd = ddeg[row];
    float v = out[i] * ((dd > 0.0f) ? (1.0f / dd) : 0.0f) + bh[d];
    out[i] = fmaxf(v, 0.0f);
}

// ---------------- launch ----------------
extern "C" void kernel_launch(void* const* d_in, const int* in_sizes, int n_in,
                              void* d_out, int out_size)
{
    const float* x    = (const float*)d_in[0];
    const void*  edge = d_in[1];
    const float* Wq = (const float*)d_in[2],  *bq  = (const float*)d_in[3];
    const float* Wk = (const float*)d_in[4],  *bk  = (const float*)d_in[5];
    const float* Wv = (const float*)d_in[6],  *bv  = (const float*)d_in[7];
    const float* Wo = (const float*)d_in[8],  *bo  = (const float*)d_in[9];
    const float* g1 = (const float*)d_in[10], *b1  = (const float*)d_in[11];
    const float* W1 = (const float*)d_in[12], *bf1 = (const float*)d_in[13];
    const float* W2 = (const float*)d_in[14], *bf2 = (const float*)d_in[15];
    const float* g2 = (const float*)d_in[16], *b2  = (const float*)d_in[17];
    const float* Wh = (const float*)d_in[18], *bh  = (const float*)d_in[19];
    float* out = (float*)d_out;

    float *h, *q, *k, *v, *o, *t, *z, *e, *bdeg, *ddeg;
    cudaGetSymbolAddress((void**)&h, g_h);
    cudaGetSymbolAddress((void**)&q, g_q);
    cudaGetSymbolAddress((void**)&k, g_k);
    cudaGetSymbolAddress((void**)&v, g_v);
    cudaGetSymbolAddress((void**)&o, g_o);
    cudaGetSymbolAddress((void**)&t, g_t);
    cudaGetSymbolAddress((void**)&z, g_z);
    cudaGetSymbolAddress((void**)&e, g_e);
    cudaGetSymbolAddress((void**)&bdeg, g_bdeg);
    cudaGetSymbolAddress((void**)&ddeg, g_ddeg);

    const int FSMEM = 4 * 64 * QP * (int)sizeof(float);  // 69632 B
    cudaFuncSetAttribute(flash_attn, cudaFuncAttributeMaxDynamicSharedMemorySize, FSMEM);

    detect_edge_kernel<<<1, 32>>>((const int*)edge);

    dim3 gD(D / 64, N / 64);       // 2 x 64
    dim3 gF(FF / 64, N / 64);      // 4 x 64
    dim3 gQKV(D / 64, N / 64, 3);  // 2 x 64 x 3

    for (int it = 0; it < 2; ++it) {
        const float* hin = (it == 0) ? x : h;
        qkv_gemm<<<gQKV, 512>>>(hin, Wq, bq, Wk, bk, Wv, bv, q, k, v);
        flash_attn<<<dim3(N / 64, H), 512, FSMEM>>>(q, k, v, o);
        sgemm_bias_act<<<gD, 512>>>(o, Wo, bo, t, D, D, 0);
        add_ln<<<N, 128>>>(hin, t, g1, b1, h);
        sgemm_bias_act<<<gF, 512>>>(h, W1, bf1, z, FF, D, 1);
        sgemm_bias_act<<<gD, 512>>>(z, W2, bf2, t, D, FF, 0);
        add_ln<<<N, 128>>>(h, t, g2, b2, h);
    }

    // xt = h @ Wh (reuse q buffer)
    sgemm_bias_act<<<gD, 512>>>(h, Wh, nullptr, q, D, D, 0);

    zero_kernel<<<(NE * D + 255) / 256, 256>>>(e, NE * D);
    zero_kernel<<<(NE + 255) / 256, 256>>>(bdeg, NE);
    zero_kernel<<<(N + 255) / 256, 256>>>(ddeg, N);
    zero_kernel<<<(N * D + 255) / 256, 256>>>(out, N * D);

    degree_kernel<<<NNZ / 256, 256>>>(edge, bdeg, ddeg);
    scatter_node_to_edge<<<(NNZ * 32) / 256, 256>>>(edge, q, e);
    scale_by_bdeg<<<(NE * D) / 256, 256>>>(e, bdeg);
    scatter_edge_to_node<<<(NNZ * 32) / 256, 256>>>(edge, e, out);
    finalize_kernel<<<(N * D) / 256, 256>>>(out, ddeg, bh);
}

// round 9
// speedup vs baseline: 1.9879x; 1.9879x over previous
#include <cuda_runtime.h>
#include <cuda_bf16.h>
#include <math.h>

#define N   4096
#define D   128
#define H   2
#define DH  64
#define FF  256
#define NE  2048
#define NNZ 65536
#define EPS 1e-5f

typedef unsigned long long u64;
typedef unsigned int u32;

// ---------------- packed f32x2 helpers ----------------
__device__ __forceinline__ u64 pack2(float lo, float hi) {
    u64 r; asm("mov.b64 %0, {%1, %2};" : "=l"(r) : "f"(lo), "f"(hi)); return r;
}
__device__ __forceinline__ void unpack2(u64 p, float& lo, float& hi) {
    asm("mov.b64 {%0, %1}, %2;" : "=f"(lo), "=f"(hi) : "l"(p));
}
__device__ __forceinline__ void fma2(u64& d, u64 a, u64 b) {
    asm("fma.rn.f32x2 %0, %1, %2, %0;" : "+l"(d) : "l"(a), "l"(b));
}

// ---------------- tf32 helpers ----------------
__device__ __forceinline__ u32 f2tf32(float x) {
    u32 r; asm("cvt.rna.tf32.f32 %0, %1;" : "=r"(r) : "f"(x)); return r;
}
__device__ __forceinline__ void mma_tf32(float& d0, float& d1, float& d2, float& d3,
                                         u32 a0, u32 a1, u32 a2, u32 a3,
                                         u32 b0, u32 b1)
{
    asm("mma.sync.aligned.m16n8k8.row.col.f32.tf32.tf32.f32 "
        "{%0,%1,%2,%3},{%4,%5,%6,%7},{%8,%9},{%0,%1,%2,%3};"
        : "+f"(d0), "+f"(d1), "+f"(d2), "+f"(d3)
        : "r"(a0), "r"(a1), "r"(a2), "r"(a3), "r"(b0), "r"(b1));
}

// ---------------- scratch (no allocation allowed) ----------------
__device__ float g_h[N * D];
__device__ float g_q[N * D];
__device__ float g_k[N * D];
__device__ float g_v[N * D];
__device__ float g_o[N * D];
__device__ float g_t[N * D];
__device__ float g_z[N * FF];
__device__ float g_e[NE * D];
__device__ float g_bdeg[NE];
__device__ float g_ddeg[N];
__device__ int   g_edge_is64;

// ---------------- edge dtype detection ----------------
__global__ void detect_edge_kernel(const int* __restrict__ e32)
{
    if (threadIdx.x == 0 && blockIdx.x == 0) {
        int is64 = 1;
        #pragma unroll
        for (int i = 1; i < 64; i += 2)
            if (e32[i] != 0) is64 = 0;
        g_edge_is64 = is64;
    }
}

__device__ __forceinline__ int2 load_edge(const void* __restrict__ edge, int nz)
{
    if (g_edge_is64) {
        const long long* e = (const long long*)edge;
        return make_int2((int)e[nz], (int)e[NNZ + nz]);
    } else {
        const int* e = (const int*)edge;
        return make_int2(e[nz], e[NNZ + nz]);
    }
}

// ------- tiled SGEMM core: 64x64 tile, KC=32, 512 threads, reg double-buffer -------
#define APAD 68
struct GemmSmem { float As[32 * APAD]; float Bs[32 * 64]; };

__device__ __forceinline__ void gemm_tile(const float* __restrict__ A,
                                          const float* __restrict__ B,
                                          const float* __restrict__ bias,
                                          float* __restrict__ C,
                                          int Nc, int K, int act,
                                          int row0, int col0, GemmSmem& sm)
{
    int tid = threadIdx.x;            // 512 threads
    int tx = tid & 15, ty = tid >> 4; // 16 x 32

    float a_reg[4], b_reg[4];
    #pragma unroll
    for (int i = 0; i < 4; i++) {
        int ia = tid + i * 512;
        int m = ia >> 5, kk = ia & 31;
        a_reg[i] = A[(size_t)(row0 + m) * K + kk];
        int kb = ia >> 6, n = ia & 63;
        b_reg[i] = B[(size_t)kb * Nc + col0 + n];
    }

    u64 acc2[2][2] = {};
    for (int k0 = 0; k0 < K; k0 += 32) {
        __syncthreads();
        #pragma unroll
        for (int i = 0; i < 4; i++) {
            int ia = tid + i * 512;
            int m = ia >> 5, kk = ia & 31;
            sm.As[kk * APAD + m] = a_reg[i];
            int kb = ia >> 6, n = ia & 63;
            sm.Bs[kb * 64 + n] = b_reg[i];
        }
        __syncthreads();
        if (k0 + 32 < K) {
            #pragma unroll
            for (int i = 0; i < 4; i++) {
                int ia = tid + i * 512;
                int m = ia >> 5, kk = ia & 31;
                a_reg[i] = A[(size_t)(row0 + m) * K + (k0 + 32) + kk];
                int kb = ia >> 6, n = ia & 63;
                b_reg[i] = B[(size_t)(k0 + 32 + kb) * Nc + col0 + n];
            }
        }
        #pragma unroll
        for (int kk = 0; kk < 32; kk++) {
            float2 a2 = *(const float2*)&sm.As[kk * APAD + ty * 2];
            float4 b4 = *(const float4*)&sm.Bs[kk * 64 + tx * 4];
            u64 b01 = pack2(b4.x, b4.y), b23 = pack2(b4.z, b4.w);
            u64 a0 = pack2(a2.x, a2.x), a1 = pack2(a2.y, a2.y);
            fma2(acc2[0][0], a0, b01); fma2(acc2[0][1], a0, b23);
            fma2(acc2[1][0], a1, b01); fma2(acc2[1][1], a1, b23);
        }
    }
    #pragma unroll
    for (int i = 0; i < 2; i++) {
        int r = row0 + ty * 2 + i;
        float vv[4];
        unpack2(acc2[i][0], vv[0], vv[1]);
        unpack2(acc2[i][1], vv[2], vv[3]);
        #pragma unroll
        for (int j = 0; j < 4; j++) {
            int c = col0 + tx * 4 + j;
            float val = vv[j] + (bias ? bias[c] : 0.0f);
            if (act == 1) val = 1.0f / (1.0f + __expf(-val));
            C[(size_t)r * Nc + c] = val;
        }
    }
}

__global__ void sgemm_bias_act(const float* __restrict__ A, const float* __restrict__ B,
                               const float* __restrict__ bias, float* __restrict__ C,
                               int Nc, int K, int act)
{
    __shared__ GemmSmem sm;
    gemm_tile(A, B, bias, C, Nc, K, act, blockIdx.y * 64, blockIdx.x * 64, sm);
}

__global__ void qkv_gemm(const float* __restrict__ A,
                         const float* __restrict__ Wq, const float* __restrict__ bq,
                         const float* __restrict__ Wk, const float* __restrict__ bk,
                         const float* __restrict__ Wv, const float* __restrict__ bv,
                         float* __restrict__ q, float* __restrict__ k, float* __restrict__ v)
{
    __shared__ GemmSmem sm;
    const float* B; const float* bias; float* C;
    if (blockIdx.z == 0)      { B = Wq; bias = bq; C = q; }
    else if (blockIdx.z == 1) { B = Wk; bias = bk; C = k; }
    else                      { B = Wv; bias = bv; C = v; }
    gemm_tile(A, B, bias, C, D, D, 0, blockIdx.y * 64, blockIdx.x * 64, sm);
}

// ======= flash attention with tf32 tensor-core MMA =======
// BM=BN=64, DH=64, 256 threads = 8 warps in 4(m) x 2(n) grid.
#define TSTR 68     // padded row stride (floats) for all tiles
__global__ void flash_attn_tc(const float* __restrict__ q, const float* __restrict__ k,
                              const float* __restrict__ v, float* __restrict__ o)
{
    extern __shared__ float fsm[];
    float* Qs = fsm;                  // [r][d]  64 x TSTR  (tf32 bits)
    float* Ks = Qs + 64 * TSTR;       // [c][d]            (tf32 bits)
    float* Vs = Ks + 64 * TSTR;       // [d][c]            (tf32 bits)
    float* Ss = Vs + 64 * TSTR;       // [r][c]  S then P(tf32)
    float* alpha_s = Ss + 64 * TSTR;  // [64]
    float* l_s     = alpha_s + 64;    // [64]
    u32* QsU = (u32*)Qs; u32* KsU = (u32*)Ks; u32* VsU = (u32*)Vs; u32* SsU = (u32*)Ss;

    int tid  = threadIdx.x;
    int wid  = tid >> 5, lane = tid & 31;
    int g    = lane >> 2, tig = lane & 3;       // mma fragment coords
    int wm   = wid & 3, wn = wid >> 2;          // warp grid 4 x 2
    int r0   = wm * 16, n0 = wn * 32;
    int qrow0 = blockIdx.x * 64;
    int hcol  = blockIdx.y * DH;

    // load Q tile (tf32)
    #pragma unroll
    for (int i = 0; i < 16; i++) {
        int idx = tid + i * 256;
        int r = idx >> 6, d = idx & 63;
        QsU[r * TSTR + d] = f2tf32(q[(size_t)(qrow0 + r) * D + hcol + d]);
    }

    // prefetch first K/V tile
    float kreg[16], vreg[16];
    #pragma unroll
    for (int i = 0; i < 16; i++) {
        int idx = tid + i * 256;
        int c = idx >> 6, d = idx & 63;
        kreg[i] = k[(size_t)c * D + hcol + d];
        vreg[i] = v[(size_t)c * D + hcol + d];
    }

    // softmax state: thread owns row sr = tid>>2, cols chunk (tid&3)*16
    int sr = tid >> 2, sc = (tid & 3) * 16;
    float m_i = -1e30f, l_i = 0.0f;
    const float scale = 0.125f;

    float of[4][4] = {};   // O fragments: [ntile][c0..c3], rows r0+g / r0+g+8, cols n0+8*nt+2*tig+{0,1}

    for (int kb = 0; kb < N; kb += 64) {
        __syncthreads();
        #pragma unroll
        for (int i = 0; i < 16; i++) {
            int idx = tid + i * 256;
            int c = idx >> 6, d = idx & 63;
            KsU[c * TSTR + d] = f2tf32(kreg[i]);
            VsU[d * TSTR + c] = f2tf32(vreg[i]);
        }
        __syncthreads();
        if (kb + 64 < N) {
            #pragma unroll
            for (int i = 0; i < 16; i++) {
                int idx = tid + i * 256;
                int c = idx >> 6, d = idx & 63;
                kreg[i] = k[(size_t)(kb + 64 + c) * D + hcol + d];
                vreg[i] = v[(size_t)(kb + 64 + c) * D + hcol + d];
            }
        }

        // ---- S = Q @ K^T (tf32 mma), warp computes 16 x 32 ----
        {
            float sf[4][4] = {};
            #pragma unroll
            for (int k0 = 0; k0 < 64; k0 += 8) {
                u32 a0 = QsU[(r0 + g) * TSTR + k0 + tig];
                u32 a1 = QsU[(r0 + g + 8) * TSTR + k0 + tig];
                u32 a2 = QsU[(r0 + g) * TSTR + k0 + tig + 4];
                u32 a3 = QsU[(r0 + g + 8) * TSTR + k0 + tig + 4];
                #pragma unroll
                for (int nt = 0; nt < 4; nt++) {
                    int n = n0 + nt * 8;
                    u32 b0 = KsU[(n + g) * TSTR + k0 + tig];
                    u32 b1 = KsU[(n + g) * TSTR + k0 + tig + 4];
                    mma_tf32(sf[nt][0], sf[nt][1], sf[nt][2], sf[nt][3],
                             a0, a1, a2, a3, b0, b1);
                }
            }
            // spill S fragments to smem
            #pragma unroll
            for (int nt = 0; nt < 4; nt++) {
                int n = n0 + nt * 8 + 2 * tig;
                *(float2*)&Ss[(r0 + g) * TSTR + n]     = make_float2(sf[nt][0], sf[nt][1]);
                *(float2*)&Ss[(r0 + g + 8) * TSTR + n] = make_float2(sf[nt][2], sf[nt][3]);
            }
        }
        __syncthreads();

        // ---- softmax: 4 threads per row, 16 cols each ----
        {
            float4 x0 = *(float4*)&Ss[sr * TSTR + sc + 0];
            float4 x1 = *(float4*)&Ss[sr * TSTR + sc + 4];
            float4 x2 = *(float4*)&Ss[sr * TSTR + sc + 8];
            float4 x3 = *(float4*)&Ss[sr * TSTR + sc + 12];
            float xs[16] = {x0.x,x0.y,x0.z,x0.w, x1.x,x1.y,x1.z,x1.w,
                            x2.x,x2.y,x2.z,x2.w, x3.x,x3.y,x3.z,x3.w};
            float mt = -1e30f;
            #pragma unroll
            for (int i = 0; i < 16; i++) { xs[i] *= scale; mt = fmaxf(mt, xs[i]); }
            mt = fmaxf(mt, __shfl_xor_sync(0xffffffffu, mt, 1));
            mt = fmaxf(mt, __shfl_xor_sync(0xffffffffu, mt, 2));
            float mnew = fmaxf(m_i, mt);
            float lt = 0.0f;
            #pragma unroll
            for (int i = 0; i < 16; i++) { xs[i] = __expf(xs[i] - mnew); lt += xs[i]; }
            lt += __shfl_xor_sync(0xffffffffu, lt, 1);
            lt += __shfl_xor_sync(0xffffffffu, lt, 2);
            float alpha = __expf(m_i - mnew);
            l_i = l_i * alpha + lt;
            m_i = mnew;
            if ((tid & 3) == 0) alpha_s[sr] = alpha;
            // store P as tf32 bits
            #pragma unroll
            for (int c4 = 0; c4 < 4; c4++) {
                uint4 pb = make_uint4(f2tf32(xs[c4*4+0]), f2tf32(xs[c4*4+1]),
                                      f2tf32(xs[c4*4+2]), f2tf32(xs[c4*4+3]));
                *(uint4*)&SsU[sr * TSTR + sc + c4 * 4] = pb;
            }
        }
        __syncthreads();

        // ---- O = alpha*O + P @ V (tf32 mma), warp computes 16 x 32 over d ----
        {
            float af  = alpha_s[r0 + g];
            float af8 = alpha_s[r0 + g + 8];
            #pragma unroll
            for (int nt = 0; nt < 4; nt++) {
                of[nt][0] *= af;  of[nt][1] *= af;
                of[nt][2] *= af8; of[nt][3] *= af8;
            }
            #pragma unroll
            for (int k0 = 0; k0 < 64; k0 += 8) {
                u32 a0 = SsU[(r0 + g) * TSTR + k0 + tig];
                u32 a1 = SsU[(r0 + g + 8) * TSTR + k0 + tig];
                u32 a2 = SsU[(r0 + g) * TSTR + k0 + tig + 4];
                u32 a3 = SsU[(r0 + g + 8) * TSTR + k0 + tig + 4];
                #pragma unroll
                for (int nt = 0; nt < 4; nt++) {
                    int n = n0 + nt * 8;
                    u32 b0 = VsU[(n + g) * TSTR + k0 + tig];
                    u32 b1 = VsU[(n + g) * TSTR + k0 + tig + 4];
                    mma_tf32(of[nt][0], of[nt][1], of[nt][2], of[nt][3],
                             a0, a1, a2, a3, b0, b1);
                }
            }
        }
    }

    // publish l, then scale and store O
    __syncthreads();
    if ((tid & 3) == 0) l_s[sr] = l_i;
    __syncthreads();
    float linv  = 1.0f / l_s[r0 + g];
    float linv8 = 1.0f / l_s[r0 + g + 8];
    #pragma unroll
    for (int nt = 0; nt < 4; nt++) {
        int n = hcol + n0 + nt * 8 + 2 * tig;
        int ra = qrow0 + r0 + g, rb = qrow0 + r0 + g + 8;
        *(float2*)&o[(size_t)ra * D + n] = make_float2(of[nt][0] * linv,  of[nt][1] * linv);
        *(float2*)&o[(size_t)rb * D + n] = make_float2(of[nt][2] * linv8, of[nt][3] * linv8);
    }
}

// ---------------- fused residual + LayerNorm ----------------
__global__ void add_ln(const float* __restrict__ hin, const float* __restrict__ t,
                       const float* __restrict__ g, const float* __restrict__ b,
                       float* __restrict__ hout)
{
    int row = blockIdx.x, tid = threadIdx.x;  // 128 threads
    float val = hin[(size_t)row * D + tid] + t[(size_t)row * D + tid];
    float s = val, s2 = val * val;
    #pragma unroll
    for (int off = 16; off >= 1; off >>= 1) {
        s  += __shfl_xor_sync(0xffffffffu, s,  off);
        s2 += __shfl_xor_sync(0xffffffffu, s2, off);
    }
    __shared__ float red[8];
    int warp = tid >> 5, lane = tid & 31;
    if (lane == 0) { red[warp] = s; red[4 + warp] = s2; }
    __syncthreads();
    s  = red[0] + red[1] + red[2] + red[3];
    s2 = red[4] + red[5] + red[6] + red[7];
    float mean = s * (1.0f / D);
    float var  = s2 * (1.0f / D) - mean * mean;
    float inv  = rsqrtf(var + EPS);
    hout[(size_t)row * D + tid] = (val - mean) * inv * g[tid] + b[tid];
}

// ---------------- hypergraph conv pieces ----------------
__global__ void zero_kernel(float* p, int n)
{
    int i = blockIdx.x * blockDim.x + threadIdx.x;
    if (i < n) p[i] = 0.0f;
}

__global__ void degree_kernel(const void* __restrict__ edge,
                              float* __restrict__ bdeg, float* __restrict__ ddeg)
{
    int i = blockIdx.x * blockDim.x + threadIdx.x;
    if (i < NNZ) {
        int2 ne = load_edge(edge, i);
        if ((unsigned)ne.x < N && (unsigned)ne.y < NE) {
            atomicAdd(&ddeg[ne.x], 1.0f);
            atomicAdd(&bdeg[ne.y], 1.0f);
        }
    }
}

__global__ void scatter_node_to_edge(const void* __restrict__ edge,
                                     const float* __restrict__ xt, float* __restrict__ e)
{
    int i = blockIdx.x * blockDim.x + threadIdx.x;   // NNZ*32 threads
    int nz = i >> 5, lane = i & 31;
    int2 ne = load_edge(edge, nz);
    if ((unsigned)ne.x >= N || (unsigned)ne.y >= NE) return;
    float4 p = *(const float4*)&xt[(size_t)ne.x * D + lane * 4];
    float* dst = &e[(size_t)ne.y * D + lane * 4];
    atomicAdd(dst + 0, p.x);
    atomicAdd(dst + 1, p.y);
    atomicAdd(dst + 2, p.z);
    atomicAdd(dst + 3, p.w);
}

__global__ void scale_by_bdeg(float* __restrict__ e, const float* __restrict__ bdeg)
{
    int i = blockIdx.x * blockDim.x + threadIdx.x;  // over NE*D
    int row = i >> 7;
    float bd = bdeg[row];
    e[i] *= (bd > 0.0f) ? (1.0f / bd) : 0.0f;
}

__global__ void scatter_edge_to_node(const void* __restrict__ edge,
                                     const float* __restrict__ e, float* __restrict__ out)
{
    int i = blockIdx.x * blockDim.x + threadIdx.x;   // NNZ*32 threads
    int nz = i >> 5, lane = i & 31;
    int2 ne = load_edge(edge, nz);
    if ((unsigned)ne.x >= N || (unsigned)ne.y >= NE) return;
    float4 p = *(const float4*)&e[(size_t)ne.y * D + lane * 4];
    float* dst = &out[(size_t)ne.x * D + lane * 4];
    atomicAdd(dst + 0, p.x);
    atomicAdd(dst + 1, p.y);
    atomicAdd(dst + 2, p.z);
    atomicAdd(dst + 3, p.w);
}

__global__ void finalize_kernel(float* __restrict__ out, const float* __restrict__ ddeg,
                                const float* __restrict__ bh)
{
    int i = blockIdx.x * blockDim.x + threadIdx.x;  // over N*D
    int row = i >> 7, d = i & 127;
    float dd = ddeg[row];
    float v = out[i] * ((dd > 0.0f) ? (1.0f / dd) : 0.0f) + bh[d];
    out[i] = fmaxf(v, 0.0f);
}

// ---------------- launch ----------------
extern "C" void kernel_launch(void* const* d_in, const int* in_sizes, int n_in,
                              void* d_out, int out_size)
{
    const float* x    = (const float*)d_in[0];
    const void*  edge = d_in[1];
    const float* Wq = (const float*)d_in[2],  *bq  = (const float*)d_in[3];
    const float* Wk = (const float*)d_in[4],  *bk  = (const float*)d_in[5];
    const float* Wv = (const float*)d_in[6],  *bv  = (const float*)d_in[7];
    const float* Wo = (const float*)d_in[8],  *bo  = (const float*)d_in[9];
    const float* g1 = (const float*)d_in[10], *b1  = (const float*)d_in[11];
    const float* W1 = (const float*)d_in[12], *bf1 = (const float*)d_in[13];
    const float* W2 = (const float*)d_in[14], *bf2 = (const float*)d_in[15];
    const float* g2 = (const float*)d_in[16], *b2  = (const float*)d_in[17];
    const float* Wh = (const float*)d_in[18], *bh  = (const float*)d_in[19];
    float* out = (float*)d_out;

    float *h, *q, *k, *v, *o, *t, *z, *e, *bdeg, *ddeg;
    cudaGetSymbolAddress((void**)&h, g_h);
    cudaGetSymbolAddress((void**)&q, g_q);
    cudaGetSymbolAddress((void**)&k, g_k);
    cudaGetSymbolAddress((void**)&v, g_v);
    cudaGetSymbolAddress((void**)&o, g_o);
    cudaGetSymbolAddress((void**)&t, g_t);
    cudaGetSymbolAddress((void**)&z, g_z);
    cudaGetSymbolAddress((void**)&e, g_e);
    cudaGetSymbolAddress((void**)&bdeg, g_bdeg);
    cudaGetSymbolAddress((void**)&ddeg, g_ddeg);

    const int FSMEM = (4 * 64 * TSTR + 128) * (int)sizeof(float);  // ~70 KB
    cudaFuncSetAttribute(flash_attn_tc, cudaFuncAttributeMaxDynamicSharedMemorySize, FSMEM);

    detect_edge_kernel<<<1, 32>>>((const int*)edge);

    dim3 gD(D / 64, N / 64);       // 2 x 64
    dim3 gF(FF / 64, N / 64);      // 4 x 64
    dim3 gQKV(D / 64, N / 64, 3);  // 2 x 64 x 3

    for (int it = 0; it < 2; ++it) {
        const float* hin = (it == 0) ? x : h;
        qkv_gemm<<<gQKV, 512>>>(hin, Wq, bq, Wk, bk, Wv, bv, q, k, v);
        flash_attn_tc<<<dim3(N / 64, H), 256, FSMEM>>>(q, k, v, o);
        sgemm_bias_act<<<gD, 512>>>(o, Wo, bo, t, D, D, 0);
        add_ln<<<N, 128>>>(hin, t, g1, b1, h);
        sgemm_bias_act<<<gF, 512>>>(h, W1, bf1, z, FF, D, 1);
        sgemm_bias_act<<<gD, 512>>>(z, W2, bf2, t, D, FF, 0);
        add_ln<<<N, 128>>>(h, t, g2, b2, h);
    }

    // xt = h @ Wh (reuse q buffer)
    sgemm_bias_act<<<gD, 512>>>(h, Wh, nullptr, q, D, D, 0);

    zero_kernel<<<(NE * D + 255) / 256, 256>>>(e, NE * D);
    zero_kernel<<<(NE + 255) / 256, 256>>>(bdeg, NE);
    zero_kernel<<<(N + 255) / 256, 256>>>(ddeg, N);
    zero_kernel<<<(N * D + 255) / 256, 256>>>(out, N * D);

    degree_kernel<<<NNZ / 256, 256>>>(edge, bdeg, ddeg);
    scatter_node_to_edge<<<(NNZ * 32) / 256, 256>>>(edge, q, e);
    scale_by_bdeg<<<(NE * D) / 256, 256>>>(e, bdeg);
    scatter_edge_to_node<<<(NNZ * 32) / 256, 256>>>(edge, e, out);
    finalize_kernel<<<(N * D) / 256, 256>>>(out, ddeg, bh);
}

// round 10
// speedup vs baseline: 2.3450x; 1.1796x over previous
#include <cuda_runtime.h>
#include <cuda_bf16.h>
#include <math.h>

#define N   4096
#define D   128
#define H   2
#define DH  64
#define FF  256
#define NE  2048
#define NNZ 65536
#define EPS 1e-5f

typedef unsigned long long u64;
typedef unsigned int u32;

// ---------------- tf32 helpers ----------------
__device__ __forceinline__ u32 f2tf32(float x) {
    u32 r; asm("cvt.rna.tf32.f32 %0, %1;" : "=r"(r) : "f"(x)); return r;
}
__device__ __forceinline__ void mma_tf32(float& d0, float& d1, float& d2, float& d3,
                                         u32 a0, u32 a1, u32 a2, u32 a3,
                                         u32 b0, u32 b1)
{
    asm("mma.sync.aligned.m16n8k8.row.col.f32.tf32.tf32.f32 "
        "{%0,%1,%2,%3},{%4,%5,%6,%7},{%8,%9},{%0,%1,%2,%3};"
        : "+f"(d0), "+f"(d1), "+f"(d2), "+f"(d3)
        : "r"(a0), "r"(a1), "r"(a2), "r"(a3), "r"(b0), "r"(b1));
}

// ---------------- scratch (no allocation allowed) ----------------
__device__ float g_h[N * D];
__device__ float g_q[N * D];
__device__ float g_k[N * D];
__device__ float g_v[N * D];
__device__ float g_o[N * D];
__device__ float g_t[N * D];
__device__ float g_z[N * FF];
__device__ float g_e[NE * D];
__device__ float g_bdeg[NE];
__device__ float g_ddeg[N];
__device__ int   g_edge_is64;

// ---------------- edge dtype detection ----------------
__global__ void detect_edge_kernel(const int* __restrict__ e32)
{
    if (threadIdx.x == 0 && blockIdx.x == 0) {
        int is64 = 1;
        #pragma unroll
        for (int i = 1; i < 64; i += 2)
            if (e32[i] != 0) is64 = 0;
        g_edge_is64 = is64;
    }
}

__device__ __forceinline__ int2 load_edge(const void* __restrict__ edge, int nz)
{
    if (g_edge_is64) {
        const long long* e = (const long long*)edge;
        return make_int2((int)e[nz], (int)e[NNZ + nz]);
    } else {
        const int* e = (const int*)edge;
        return make_int2(e[nz], e[NNZ + nz]);
    }
}

// ======= tf32 tensor-core GEMM: C = act(A @ B + bias), 64x64 tile, KC=32 =======
// 256 threads = 8 warps in 4(m) x 2(n); warp tile 16 x 32.
#define GSTR 36
struct GemmTcSmem { u32 As[64 * GSTR]; u32 Bs[64 * GSTR]; };

__device__ __forceinline__ void gemm_tile_tc(const float* __restrict__ A,
                                             const float* __restrict__ B,
                                             const float* __restrict__ bias,
                                             float* __restrict__ C,
                                             int Nc, int K, int act,
                                             int row0, int col0, GemmTcSmem& sm)
{
    int tid = threadIdx.x;
    int wid = tid >> 5, lane = tid & 31;
    int g = lane >> 2, tig = lane & 3;
    int wm = wid & 3, wn = wid >> 2;
    int r0 = wm * 16, n0 = wn * 32;

    float areg[8], breg[8];
    #pragma unroll
    for (int i = 0; i < 8; i++) {
        int idx = tid + i * 256;
        int am = idx >> 5, ak = idx & 31;
        areg[i] = A[(size_t)(row0 + am) * K + ak];
        int bk = idx >> 6, bn = idx & 63;
        breg[i] = B[(size_t)bk * Nc + col0 + bn];
    }

    float acc[4][4] = {};
    for (int k0 = 0; k0 < K; k0 += 32) {
        __syncthreads();
        #pragma unroll
        for (int i = 0; i < 8; i++) {
            int idx = tid + i * 256;
            int am = idx >> 5, ak = idx & 31;
            sm.As[am * GSTR + ak] = f2tf32(areg[i]);
            int bk = idx >> 6, bn = idx & 63;
            sm.Bs[bn * GSTR + bk] = f2tf32(breg[i]);
        }
        __syncthreads();
        if (k0 + 32 < K) {
            #pragma unroll
            for (int i = 0; i < 8; i++) {
                int idx = tid + i * 256;
                int am = idx >> 5, ak = idx & 31;
                areg[i] = A[(size_t)(row0 + am) * K + (k0 + 32) + ak];
                int bk = idx >> 6, bn = idx & 63;
                breg[i] = B[(size_t)(k0 + 32 + bk) * Nc + col0 + bn];
            }
        }
        #pragma unroll
        for (int ks = 0; ks < 4; ks++) {
            int kk = ks * 8;
            u32 a0 = sm.As[(r0 + g) * GSTR + kk + tig];
            u32 a1 = sm.As[(r0 + g + 8) * GSTR + kk + tig];
            u32 a2 = sm.As[(r0 + g) * GSTR + kk + tig + 4];
            u32 a3 = sm.As[(r0 + g + 8) * GSTR + kk + tig + 4];
            #pragma unroll
            for (int nt = 0; nt < 4; nt++) {
                int n = n0 + nt * 8;
                u32 b0 = sm.Bs[(n + g) * GSTR + kk + tig];
                u32 b1 = sm.Bs[(n + g) * GSTR + kk + tig + 4];
                mma_tf32(acc[nt][0], acc[nt][1], acc[nt][2], acc[nt][3],
                         a0, a1, a2, a3, b0, b1);
            }
        }
    }

    int ra = row0 + r0 + g, rb = ra + 8;
    #pragma unroll
    for (int nt = 0; nt < 4; nt++) {
        int c = col0 + n0 + nt * 8 + 2 * tig;
        float bc0 = bias ? bias[c] : 0.0f;
        float bc1 = bias ? bias[c + 1] : 0.0f;
        float v0 = acc[nt][0] + bc0, v1 = acc[nt][1] + bc1;
        float v2 = acc[nt][2] + bc0, v3 = acc[nt][3] + bc1;
        if (act == 1) {
            v0 = 1.0f / (1.0f + __expf(-v0));
            v1 = 1.0f / (1.0f + __expf(-v1));
            v2 = 1.0f / (1.0f + __expf(-v2));
            v3 = 1.0f / (1.0f + __expf(-v3));
        }
        *(float2*)&C[(size_t)ra * Nc + c] = make_float2(v0, v1);
        *(float2*)&C[(size_t)rb * Nc + c] = make_float2(v2, v3);
    }
}

__global__ void gemm_tc(const float* __restrict__ A, const float* __restrict__ B,
                        const float* __restrict__ bias, float* __restrict__ C,
                        int Nc, int K, int act)
{
    __shared__ GemmTcSmem sm;
    gemm_tile_tc(A, B, bias, C, Nc, K, act, blockIdx.y * 64, blockIdx.x * 64, sm);
}

__global__ void qkv_gemm_tc(const float* __restrict__ A,
                            const float* __restrict__ Wq, const float* __restrict__ bq,
                            const float* __restrict__ Wk, const float* __restrict__ bk,
                            const float* __restrict__ Wv, const float* __restrict__ bv,
                            float* __restrict__ q, float* __restrict__ k, float* __restrict__ v)
{
    __shared__ GemmTcSmem sm;
    const float* B; const float* bias; float* C;
    if (blockIdx.z == 0)      { B = Wq; bias = bq; C = q; }
    else if (blockIdx.z == 1) { B = Wk; bias = bk; C = k; }
    else                      { B = Wv; bias = bv; C = v; }
    gemm_tile_tc(A, B, bias, C, D, D, 0, blockIdx.y * 64, blockIdx.x * 64, sm);
}

// ======= flash attention with tf32 tensor-core MMA =======
// BM=BN=64, DH=64, 256 threads = 8 warps in 4(m) x 2(n) grid.
#define TSTR 68
__global__ void flash_attn_tc(const float* __restrict__ q, const float* __restrict__ k,
                              const float* __restrict__ v, float* __restrict__ o)
{
    extern __shared__ float fsm[];
    float* Qs = fsm;                  // [r][d]
    float* Ks = Qs + 64 * TSTR;       // [c][d]
    float* Vs = Ks + 64 * TSTR;       // [d][c]
    float* Ss = Vs + 64 * TSTR;       // [r][c]
    float* alpha_s = Ss + 64 * TSTR;  // [64]
    float* l_s     = alpha_s + 64;    // [64]
    u32* QsU = (u32*)Qs; u32* KsU = (u32*)Ks; u32* VsU = (u32*)Vs; u32* SsU = (u32*)Ss;

    int tid  = threadIdx.x;
    int wid  = tid >> 5, lane = tid & 31;
    int g    = lane >> 2, tig = lane & 3;
    int wm   = wid & 3, wn = wid >> 2;
    int r0   = wm * 16, n0 = wn * 32;
    int qrow0 = blockIdx.x * 64;
    int hcol  = blockIdx.y * DH;

    #pragma unroll
    for (int i = 0; i < 16; i++) {
        int idx = tid + i * 256;
        int r = idx >> 6, d = idx & 63;
        QsU[r * TSTR + d] = f2tf32(q[(size_t)(qrow0 + r) * D + hcol + d]);
    }

    float kreg[16], vreg[16];
    #pragma unroll
    for (int i = 0; i < 16; i++) {
        int idx = tid + i * 256;
        int c = idx >> 6, d = idx & 63;
        kreg[i] = k[(size_t)c * D + hcol + d];
        vreg[i] = v[(size_t)c * D + hcol + d];
    }

    int sr = tid >> 2, sc = (tid & 3) * 16;
    float m_i = -1e30f, l_i = 0.0f;
    const float scale = 0.125f;

    float of[4][4] = {};

    for (int kb = 0; kb < N; kb += 64) {
        __syncthreads();
        #pragma unroll
        for (int i = 0; i < 16; i++) {
            int idx = tid + i * 256;
            int c = idx >> 6, d = idx & 63;
            KsU[c * TSTR + d] = f2tf32(kreg[i]);
            VsU[d * TSTR + c] = f2tf32(vreg[i]);
        }
        __syncthreads();
        if (kb + 64 < N) {
            #pragma unroll
            for (int i = 0; i < 16; i++) {
                int idx = tid + i * 256;
                int c = idx >> 6, d = idx & 63;
                kreg[i] = k[(size_t)(kb + 64 + c) * D + hcol + d];
                vreg[i] = v[(size_t)(kb + 64 + c) * D + hcol + d];
            }
        }

        // S = Q @ K^T
        {
            float sf[4][4] = {};
            #pragma unroll
            for (int k0 = 0; k0 < 64; k0 += 8) {
                u32 a0 = QsU[(r0 + g) * TSTR + k0 + tig];
                u32 a1 = QsU[(r0 + g + 8) * TSTR + k0 + tig];
                u32 a2 = QsU[(r0 + g) * TSTR + k0 + tig + 4];
                u32 a3 = QsU[(r0 + g + 8) * TSTR + k0 + tig + 4];
                #pragma unroll
                for (int nt = 0; nt < 4; nt++) {
                    int n = n0 + nt * 8;
                    u32 b0 = KsU[(n + g) * TSTR + k0 + tig];
                    u32 b1 = KsU[(n + g) * TSTR + k0 + tig + 4];
                    mma_tf32(sf[nt][0], sf[nt][1], sf[nt][2], sf[nt][3],
                             a0, a1, a2, a3, b0, b1);
                }
            }
            #pragma unroll
            for (int nt = 0; nt < 4; nt++) {
                int n = n0 + nt * 8 + 2 * tig;
                *(float2*)&Ss[(r0 + g) * TSTR + n]     = make_float2(sf[nt][0], sf[nt][1]);
                *(float2*)&Ss[(r0 + g + 8) * TSTR + n] = make_float2(sf[nt][2], sf[nt][3]);
            }
        }
        __syncthreads();

        // softmax: 4 threads per row, 16 cols each
        {
            float4 x0 = *(float4*)&Ss[sr * TSTR + sc + 0];
            float4 x1 = *(float4*)&Ss[sr * TSTR + sc + 4];
            float4 x2 = *(float4*)&Ss[sr * TSTR + sc + 8];
            float4 x3 = *(float4*)&Ss[sr * TSTR + sc + 12];
            float xs[16] = {x0.x,x0.y,x0.z,x0.w, x1.x,x1.y,x1.z,x1.w,
                            x2.x,x2.y,x2.z,x2.w, x3.x,x3.y,x3.z,x3.w};
            float mt = -1e30f;
            #pragma unroll
            for (int i = 0; i < 16; i++) { xs[i] *= scale; mt = fmaxf(mt, xs[i]); }
            mt = fmaxf(mt, __shfl_xor_sync(0xffffffffu, mt, 1));
            mt = fmaxf(mt, __shfl_xor_sync(0xffffffffu, mt, 2));
            float mnew = fmaxf(m_i, mt);
            float lt = 0.0f;
            #pragma unroll
            for (int i = 0; i < 16; i++) { xs[i] = __expf(xs[i] - mnew); lt += xs[i]; }
            lt += __shfl_xor_sync(0xffffffffu, lt, 1);
            lt += __shfl_xor_sync(0xffffffffu, lt, 2);
            float alpha = __expf(m_i - mnew);
            l_i = l_i * alpha + lt;
            m_i = mnew;
            if ((tid & 3) == 0) alpha_s[sr] = alpha;
            #pragma unroll
            for (int c4 = 0; c4 < 4; c4++) {
                uint4 pb = make_uint4(f2tf32(xs[c4*4+0]), f2tf32(xs[c4*4+1]),
                                      f2tf32(xs[c4*4+2]), f2tf32(xs[c4*4+3]));
                *(uint4*)&SsU[sr * TSTR + sc + c4 * 4] = pb;
            }
        }
        __syncthreads();

        // O = alpha*O + P @ V
        {
            float af  = alpha_s[r0 + g];
            float af8 = alpha_s[r0 + g + 8];
            #pragma unroll
            for (int nt = 0; nt < 4; nt++) {
                of[nt][0] *= af;  of[nt][1] *= af;
                of[nt][2] *= af8; of[nt][3] *= af8;
            }
            #pragma unroll
            for (int k0 = 0; k0 < 64; k0 += 8) {
                u32 a0 = SsU[(r0 + g) * TSTR + k0 + tig];
                u32 a1 = SsU[(r0 + g + 8) * TSTR + k0 + tig];
                u32 a2 = SsU[(r0 + g) * TSTR + k0 + tig + 4];
                u32 a3 = SsU[(r0 + g + 8) * TSTR + k0 + tig + 4];
                #pragma unroll
                for (int nt = 0; nt < 4; nt++) {
                    int n = n0 + nt * 8;
                    u32 b0 = VsU[(n + g) * TSTR + k0 + tig];
                    u32 b1 = VsU[(n + g) * TSTR + k0 + tig + 4];
                    mma_tf32(of[nt][0], of[nt][1], of[nt][2], of[nt][3],
                             a0, a1, a2, a3, b0, b1);
                }
            }
        }
    }

    __syncthreads();
    if ((tid & 3) == 0) l_s[sr] = l_i;
    __syncthreads();
    float linv  = 1.0f / l_s[r0 + g];
    float linv8 = 1.0f / l_s[r0 + g + 8];
    #pragma unroll
    for (int nt = 0; nt < 4; nt++) {
        int n = hcol + n0 + nt * 8 + 2 * tig;
        int ra = qrow0 + r0 + g, rb = qrow0 + r0 + g + 8;
        *(float2*)&o[(size_t)ra * D + n] = make_float2(of[nt][0] * linv,  of[nt][1] * linv);
        *(float2*)&o[(size_t)rb * D + n] = make_float2(of[nt][2] * linv8, of[nt][3] * linv8);
    }
}

// ---------------- fused residual + LayerNorm ----------------
__global__ void add_ln(const float* __restrict__ hin, const float* __restrict__ t,
                       const float* __restrict__ g, const float* __restrict__ b,
                       float* __restrict__ hout)
{
    int row = blockIdx.x, tid = threadIdx.x;  // 128 threads
    float val = hin[(size_t)row * D + tid] + t[(size_t)row * D + tid];
    float s = val, s2 = val * val;
    #pragma unroll
    for (int off = 16; off >= 1; off >>= 1) {
        s  += __shfl_xor_sync(0xffffffffu, s,  off);
        s2 += __shfl_xor_sync(0xffffffffu, s2, off);
    }
    __shared__ float red[8];
    int warp = tid >> 5, lane = tid & 31;
    if (lane == 0) { red[warp] = s; red[4 + warp] = s2; }
    __syncthreads();
    s  = red[0] + red[1] + red[2] + red[3];
    s2 = red[4] + red[5] + red[6] + red[7];
    float mean = s * (1.0f / D);
    float var  = s2 * (1.0f / D) - mean * mean;
    float inv  = rsqrtf(var + EPS);
    hout[(size_t)row * D + tid] = (val - mean) * inv * g[tid] + b[tid];
}

// ---------------- hypergraph conv pieces ----------------
__global__ void zero_kernel(float* p, int n)
{
    int i = blockIdx.x * blockDim.x + threadIdx.x;
    if (i < n) p[i] = 0.0f;
}

__global__ void degree_kernel(const void* __restrict__ edge,
                              float* __restrict__ bdeg, float* __restrict__ ddeg)
{
    int i = blockIdx.x * blockDim.x + threadIdx.x;
    if (i < NNZ) {
        int2 ne = load_edge(edge, i);
        if ((unsigned)ne.x < N && (unsigned)ne.y < NE) {
            atomicAdd(&ddeg[ne.x], 1.0f);
            atomicAdd(&bdeg[ne.y], 1.0f);
        }
    }
}

__global__ void scatter_node_to_edge(const void* __restrict__ edge,
                                     const float* __restrict__ xt, float* __restrict__ e)
{
    int i = blockIdx.x * blockDim.x + threadIdx.x;   // NNZ*32 threads
    int nz = i >> 5, lane = i & 31;
    int2 ne = load_edge(edge, nz);
    if ((unsigned)ne.x >= N || (unsigned)ne.y >= NE) return;
    float4 p = *(const float4*)&xt[(size_t)ne.x * D + lane * 4];
    float* dst = &e[(size_t)ne.y * D + lane * 4];
    atomicAdd(dst + 0, p.x);
    atomicAdd(dst + 1, p.y);
    atomicAdd(dst + 2, p.z);
    atomicAdd(dst + 3, p.w);
}

// gathers e[he]*Binv[he] and scatters into out[node]  (scale fused)
__global__ void scatter_edge_to_node(const void* __restrict__ edge,
                                     const float* __restrict__ e,
                                     const float* __restrict__ bdeg,
                                     float* __restrict__ out)
{
    int i = blockIdx.x * blockDim.x + threadIdx.x;   // NNZ*32 threads
    int nz = i >> 5, lane = i & 31;
    int2 ne = load_edge(edge, nz);
    if ((unsigned)ne.x >= N || (unsigned)ne.y >= NE) return;
    float bd = bdeg[ne.y];
    float bi = (bd > 0.0f) ? (1.0f / bd) : 0.0f;
    float4 p = *(const float4*)&e[(size_t)ne.y * D + lane * 4];
    float* dst = &out[(size_t)ne.x * D + lane * 4];
    atomicAdd(dst + 0, p.x * bi);
    atomicAdd(dst + 1, p.y * bi);
    atomicAdd(dst + 2, p.z * bi);
    atomicAdd(dst + 3, p.w * bi);
}

__global__ void finalize_kernel(float* __restrict__ out, const float* __restrict__ ddeg,
                                const float* __restrict__ bh)
{
    int i = blockIdx.x * blockDim.x + threadIdx.x;  // over N*D
    int row = i >> 7, d = i & 127;
    float dd = ddeg[row];
    float v = out[i] * ((dd > 0.0f) ? (1.0f / dd) : 0.0f) + bh[d];
    out[i] = fmaxf(v, 0.0f);
}

// ---------------- launch ----------------
extern "C" void kernel_launch(void* const* d_in, const int* in_sizes, int n_in,
                              void* d_out, int out_size)
{
    const float* x    = (const float*)d_in[0];
    const void*  edge = d_in[1];
    const float* Wq = (const float*)d_in[2],  *bq  = (const float*)d_in[3];
    const float* Wk = (const float*)d_in[4],  *bk  = (const float*)d_in[5];
    const float* Wv = (const float*)d_in[6],  *bv  = (const float*)d_in[7];
    const float* Wo = (const float*)d_in[8],  *bo  = (const float*)d_in[9];
    const float* g1 = (const float*)d_in[10], *b1  = (const float*)d_in[11];
    const float* W1 = (const float*)d_in[12], *bf1 = (const float*)d_in[13];
    const float* W2 = (const float*)d_in[14], *bf2 = (const float*)d_in[15];
    const float* g2 = (const float*)d_in[16], *b2  = (const float*)d_in[17];
    const float* Wh = (const float*)d_in[18], *bh  = (const float*)d_in[19];
    float* out = (float*)d_out;

    float *h, *q, *k, *v, *o, *t, *z, *e, *bdeg, *ddeg;
    cudaGetSymbolAddress((void**)&h, g_h);
    cudaGetSymbolAddress((void**)&q, g_q);
    cudaGetSymbolAddress((void**)&k, g_k);
    cudaGetSymbolAddress((void**)&v, g_v);
    cudaGetSymbolAddress((void**)&o, g_o);
    cudaGetSymbolAddress((void**)&t, g_t);
    cudaGetSymbolAddress((void**)&z, g_z);
    cudaGetSymbolAddress((void**)&e, g_e);
    cudaGetSymbolAddress((void**)&bdeg, g_bdeg);
    cudaGetSymbolAddress((void**)&ddeg, g_ddeg);

    const int FSMEM = (4 * 64 * TSTR + 128) * (int)sizeof(float);  // ~70 KB
    cudaFuncSetAttribute(flash_attn_tc, cudaFuncAttributeMaxDynamicSharedMemorySize, FSMEM);

    detect_edge_kernel<<<1, 32>>>((const int*)edge);

    dim3 gD(D / 64, N / 64);       // 2 x 64
    dim3 gF(FF / 64, N / 64);      // 4 x 64
    dim3 gQKV(D / 64, N / 64, 3);  // 2 x 64 x 3

    for (int it = 0; it < 2; ++it) {
        const float* hin = (it == 0) ? x : h;
        qkv_gemm_tc<<<gQKV, 256>>>(hin, Wq, bq, Wk, bk, Wv, bv, q, k, v);
        flash_attn_tc<<<dim3(N / 64, H), 256, FSMEM>>>(q, k, v, o);
        gemm_tc<<<gD, 256>>>(o, Wo, bo, t, D, D, 0);
        add_ln<<<N, 128>>>(hin, t, g1, b1, h);
        gemm_tc<<<gF, 256>>>(h, W1, bf1, z, FF, D, 1);
        gemm_tc<<<gD, 256>>>(z, W2, bf2, t, D, FF, 0);
        add_ln<<<N, 128>>>(h, t, g2, b2, h);
    }

    // xt = h @ Wh (reuse q buffer)
    gemm_tc<<<gD, 256>>>(h, Wh, nullptr, q, D, D, 0);

    zero_kernel<<<(NE * D + 255) / 256, 256>>>(e, NE * D);
    zero_kernel<<<(NE + 255) / 256, 256>>>(bdeg, NE);
    zero_kernel<<<(N + 255) / 256, 256>>>(ddeg, N);
    zero_kernel<<<(N * D + 255) / 256, 256>>>(out, N * D);

    degree_kernel<<<NNZ / 256, 256>>>(edge, bdeg, ddeg);
    scatter_node_to_edge<<<(NNZ * 32) / 256, 256>>>(edge, q, e);
    scatter_edge_to_node<<<(NNZ * 32) / 256, 256>>>(edge, e, bdeg, out);
    finalize_kernel<<<(N * D) / 256, 256>>>(out, ddeg, bh);
}

// round 12
// speedup vs baseline: 2.5062x; 1.0687x over previous
#include <cuda_runtime.h>
#include <cuda_bf16.h>
#include <math.h>

#define N   4096
#define D   128
#define H   2
#define DH  64
#define FF  256
#define NE  2048
#define NNZ 65536
#define EPS 1e-5f

typedef unsigned long long u64;
typedef unsigned int u32;

// ---------------- tf32 helpers ----------------
__device__ __forceinline__ u32 f2tf32(float x) {
    u32 r; asm("cvt.rna.tf32.f32 %0, %1;" : "=r"(r) : "f"(x)); return r;
}
__device__ __forceinline__ void mma_tf32(float& d0, float& d1, float& d2, float& d3,
                                         u32 a0, u32 a1, u32 a2, u32 a3,
                                         u32 b0, u32 b1)
{
    asm("mma.sync.aligned.m16n8k8.row.col.f32.tf32.tf32.f32 "
        "{%0,%1,%2,%3},{%4,%5,%6,%7},{%8,%9},{%0,%1,%2,%3};"
        : "+f"(d0), "+f"(d1), "+f"(d2), "+f"(d3)
        : "r"(a0), "r"(a1), "r"(a2), "r"(a3), "r"(b0), "r"(b1));
}

// ---------------- scratch (no allocation allowed) ----------------
__device__ float g_h[N * D];
__device__ float g_q[N * D];
__device__ float g_k[N * D];
__device__ float g_v[N * D];
__device__ float g_o[N * D];
__device__ float g_z[N * FF];
__device__ float g_e[NE * D];
__device__ float g_bdeg[NE];
__device__ float g_ddeg[N];
__device__ int   g_edge_is64;

// ---------------- edge dtype detection ----------------
__global__ void detect_edge_kernel(const int* __restrict__ e32)
{
    if (threadIdx.x == 0 && blockIdx.x == 0) {
        int is64 = 1;
        #pragma unroll
        for (int i = 1; i < 64; i += 2)
            if (e32[i] != 0) is64 = 0;
        g_edge_is64 = is64;
    }
}

__device__ __forceinline__ int2 load_edge(const void* __restrict__ edge, int nz)
{
    if (g_edge_is64) {
        const long long* e = (const long long*)edge;
        return make_int2((int)e[nz], (int)e[NNZ + nz]);
    } else {
        const int* e = (const int*)edge;
        return make_int2(e[nz], e[NNZ + nz]);
    }
}

// ======= tf32 tensor-core GEMM: C = act(A @ B + bias), 64x64 tile, KC=32 =======
#define GSTR 36
struct GemmTcSmem { u32 As[64 * GSTR]; u32 Bs[64 * GSTR]; };

__device__ __forceinline__ void gemm_tile_tc(const float* __restrict__ A,
                                             const float* __restrict__ B,
                                             const float* __restrict__ bias,
                                             float* __restrict__ C,
                                             int Nc, int K, int act,
                                             int row0, int col0, GemmTcSmem& sm)
{
    int tid = threadIdx.x;
    int wid = tid >> 5, lane = tid & 31;
    int g = lane >> 2, tig = lane & 3;
    int wm = wid & 3, wn = wid >> 2;
    int r0 = wm * 16, n0 = wn * 32;

    float areg[8], breg[8];
    #pragma unroll
    for (int i = 0; i < 8; i++) {
        int idx = tid + i * 256;
        int am = idx >> 5, ak = idx & 31;
        areg[i] = A[(size_t)(row0 + am) * K + ak];
        int bk = idx >> 6, bn = idx & 63;
        breg[i] = B[(size_t)bk * Nc + col0 + bn];
    }

    float acc[4][4] = {};
    for (int k0 = 0; k0 < K; k0 += 32) {
        __syncthreads();
        #pragma unroll
        for (int i = 0; i < 8; i++) {
            int idx = tid + i * 256;
            int am = idx >> 5, ak = idx & 31;
            sm.As[am * GSTR + ak] = f2tf32(areg[i]);
            int bk = idx >> 6, bn = idx & 63;
            sm.Bs[bn * GSTR + bk] = f2tf32(breg[i]);
        }
        __syncthreads();
        if (k0 + 32 < K) {
            #pragma unroll
            for (int i = 0; i < 8; i++) {
                int idx = tid + i * 256;
                int am = idx >> 5, ak = idx & 31;
                areg[i] = A[(size_t)(row0 + am) * K + (k0 + 32) + ak];
                int bk = idx >> 6, bn = idx & 63;
                breg[i] = B[(size_t)(k0 + 32 + bk) * Nc + col0 + bn];
            }
        }
        #pragma unroll
        for (int ks = 0; ks < 4; ks++) {
            int kk = ks * 8;
            u32 a0 = sm.As[(r0 + g) * GSTR + kk + tig];
            u32 a1 = sm.As[(r0 + g + 8) * GSTR + kk + tig];
            u32 a2 = sm.As[(r0 + g) * GSTR + kk + tig + 4];
            u32 a3 = sm.As[(r0 + g + 8) * GSTR + kk + tig + 4];
            #pragma unroll
            for (int nt = 0; nt < 4; nt++) {
                int n = n0 + nt * 8;
                u32 b0 = sm.Bs[(n + g) * GSTR + kk + tig];
                u32 b1 = sm.Bs[(n + g) * GSTR + kk + tig + 4];
                mma_tf32(acc[nt][0], acc[nt][1], acc[nt][2], acc[nt][3],
                         a0, a1, a2, a3, b0, b1);
            }
        }
    }

    int ra = row0 + r0 + g, rb = ra + 8;
    #pragma unroll
    for (int nt = 0; nt < 4; nt++) {
        int c = col0 + n0 + nt * 8 + 2 * tig;
        float bc0 = bias ? bias[c] : 0.0f;
        float bc1 = bias ? bias[c + 1] : 0.0f;
        float v0 = acc[nt][0] + bc0, v1 = acc[nt][1] + bc1;
        float v2 = acc[nt][2] + bc0, v3 = acc[nt][3] + bc1;
        if (act == 1) {
            v0 = 1.0f / (1.0f + __expf(-v0));
            v1 = 1.0f / (1.0f + __expf(-v1));
            v2 = 1.0f / (1.0f + __expf(-v2));
            v3 = 1.0f / (1.0f + __expf(-v3));
        }
        *(float2*)&C[(size_t)ra * Nc + c] = make_float2(v0, v1);
        *(float2*)&C[(size_t)rb * Nc + c] = make_float2(v2, v3);
    }
}

__global__ void gemm_tc(const float* __restrict__ A, const float* __restrict__ B,
                        const float* __restrict__ bias, float* __restrict__ C,
                        int Nc, int K, int act)
{
    __shared__ GemmTcSmem sm;
    gemm_tile_tc(A, B, bias, C, Nc, K, act, blockIdx.y * 64, blockIdx.x * 64, sm);
}

__global__ void qkv_gemm_tc(const float* __restrict__ A,
                            const float* __restrict__ Wq, const float* __restrict__ bq,
                            const float* __restrict__ Wk, const float* __restrict__ bk,
                            const float* __restrict__ Wv, const float* __restrict__ bv,
                            float* __restrict__ q, float* __restrict__ k, float* __restrict__ v)
{
    __shared__ GemmTcSmem sm;
    const float* B; const float* bias; float* C;
    if (blockIdx.z == 0)      { B = Wq; bias = bq; C = q; }
    else if (blockIdx.z == 1) { B = Wk; bias = bk; C = k; }
    else                      { B = Wv; bias = bv; C = v; }
    gemm_tile_tc(A, B, bias, C, D, D, 0, blockIdx.y * 64, blockIdx.x * 64, sm);
}

// ======= fused GEMM + residual + LayerNorm: C = LN(hin + A@B + bias) =======
// Tile 64 rows x 128 cols (full D). 256 threads, 8 warps 4(m) x 2(n), warp tile 16x64.
struct GemmLnSmem {
    u32 As[64 * GSTR];
    u32 Bs[128 * GSTR];
    float ps[64 * 2];   // row partial sums   [row][wn]
    float pq[64 * 2];   // row partial sumsq  [row][wn]
};

__global__ void gemm_ln_tc(const float* __restrict__ A, const float* __restrict__ B,
                           const float* __restrict__ bias, const float* __restrict__ hin,
                           const float* __restrict__ lng, const float* __restrict__ lnb,
                           float* __restrict__ C, int K)
{
    __shared__ GemmLnSmem sm;
    int tid = threadIdx.x;
    int wid = tid >> 5, lane = tid & 31;
    int gq = lane >> 2, tig = lane & 3;
    int wm = wid & 3, wn = wid >> 2;
    int r0 = wm * 16, n0 = wn * 64;
    int row0 = blockIdx.x * 64;

    float areg[8], breg[16];
    #pragma unroll
    for (int i = 0; i < 8; i++) {
        int idx = tid + i * 256;
        int am = idx >> 5, ak = idx & 31;
        areg[i] = A[(size_t)(row0 + am) * K + ak];
    }
    #pragma unroll
    for (int i = 0; i < 16; i++) {
        int idx = tid + i * 256;
        int bk = idx >> 7, bn = idx & 127;
        breg[i] = B[(size_t)bk * D + bn];
    }

    float acc[8][4] = {};
    for (int k0 = 0; k0 < K; k0 += 32) {
        __syncthreads();
        #pragma unroll
        for (int i = 0; i < 8; i++) {
            int idx = tid + i * 256;
            int am = idx >> 5, ak = idx & 31;
            sm.As[am * GSTR + ak] = f2tf32(areg[i]);
        }
        #pragma unroll
        for (int i = 0; i < 16; i++) {
            int idx = tid + i * 256;
            int bk = idx >> 7, bn = idx & 127;
            sm.Bs[bn * GSTR + bk] = f2tf32(breg[i]);
        }
        __syncthreads();
        if (k0 + 32 < K) {
            #pragma unroll
            for (int i = 0; i < 8; i++) {
                int idx = tid + i * 256;
                int am = idx >> 5, ak = idx & 31;
                areg[i] = A[(size_t)(row0 + am) * K + (k0 + 32) + ak];
            }
            #pragma unroll
            for (int i = 0; i < 16; i++) {
                int idx = tid + i * 256;
                int bk = idx >> 7, bn = idx & 127;
                breg[i] = B[(size_t)(k0 + 32 + bk) * D + bn];
            }
        }
        #pragma unroll
        for (int ks = 0; ks < 4; ks++) {
            int kk = ks * 8;
            u32 a0 = sm.As[(r0 + gq) * GSTR + kk + tig];
            u32 a1 = sm.As[(r0 + gq + 8) * GSTR + kk + tig];
            u32 a2 = sm.As[(r0 + gq) * GSTR + kk + tig + 4];
            u32 a3 = sm.As[(r0 + gq + 8) * GSTR + kk + tig + 4];
            #pragma unroll
            for (int nt = 0; nt < 8; nt++) {
                int n = n0 + nt * 8;
                u32 b0 = sm.Bs[(n + gq) * GSTR + kk + tig];
                u32 b1 = sm.Bs[(n + gq) * GSTR + kk + tig + 4];
                mma_tf32(acc[nt][0], acc[nt][1], acc[nt][2], acc[nt][3],
                         a0, a1, a2, a3, b0, b1);
            }
        }
    }

    // epilogue: residual + bias, then row LN stats via quad shfl + 2-way partials
    int ra = row0 + r0 + gq, rb = ra + 8;
    float va[8][2], vb[8][2];
    float sa = 0.0f, qa = 0.0f, sb = 0.0f, qb = 0.0f;
    #pragma unroll
    for (int nt = 0; nt < 8; nt++) {
        int c = n0 + nt * 8 + 2 * tig;
        float2 bc  = *(const float2*)&bias[c];
        float2 ha  = *(const float2*)&hin[(size_t)ra * D + c];
        float2 hb  = *(const float2*)&hin[(size_t)rb * D + c];
        va[nt][0] = acc[nt][0] + bc.x + ha.x;
        va[nt][1] = acc[nt][1] + bc.y + ha.y;
        vb[nt][0] = acc[nt][2] + bc.x + hb.x;
        vb[nt][1] = acc[nt][3] + bc.y + hb.y;
        sa += va[nt][0] + va[nt][1];
        qa += va[nt][0] * va[nt][0] + va[nt][1] * va[nt][1];
        sb += vb[nt][0] + vb[nt][1];
        qb += vb[nt][0] * vb[nt][0] + vb[nt][1] * vb[nt][1];
    }
    #pragma unroll
    for (int off = 1; off <= 2; off <<= 1) {
        sa += __shfl_xor_sync(0xffffffffu, sa, off);
        qa += __shfl_xor_sync(0xffffffffu, qa, off);
        sb += __shfl_xor_sync(0xffffffffu, sb, off);
        qb += __shfl_xor_sync(0xffffffffu, qb, off);
    }
    if (tig == 0) {
        sm.ps[(r0 + gq) * 2 + wn] = sa;     sm.pq[(r0 + gq) * 2 + wn] = qa;
        sm.ps[(r0 + gq + 8) * 2 + wn] = sb; sm.pq[(r0 + gq + 8) * 2 + wn] = qb;
    }
    __syncthreads();
    float Sa = sm.ps[(r0 + gq) * 2] + sm.ps[(r0 + gq) * 2 + 1];
    float Qa = sm.pq[(r0 + gq) * 2] + sm.pq[(r0 + gq) * 2 + 1];
    float Sb = sm.ps[(r0 + gq + 8) * 2] + sm.ps[(r0 + gq + 8) * 2 + 1];
    float Qb = sm.pq[(r0 + gq + 8) * 2] + sm.pq[(r0 + gq + 8) * 2 + 1];
    float ma = Sa * (1.0f / D), vva = Qa * (1.0f / D) - ma * ma;
    float mb = Sb * (1.0f / D), vvb = Qb * (1.0f / D) - mb * mb;
    float ia = rsqrtf(vva + EPS), ib = rsqrtf(vvb + EPS);
    #pragma unroll
    for (int nt = 0; nt < 8; nt++) {
        int c = n0 + nt * 8 + 2 * tig;
        float2 gg = *(const float2*)&lng[c];
        float2 bb = *(const float2*)&lnb[c];
        *(float2*)&C[(size_t)ra * D + c] =
            make_float2((va[nt][0] - ma) * ia * gg.x + bb.x,
                        (va[nt][1] - ma) * ia * gg.y + bb.y);
        *(float2*)&C[(size_t)rb * D + c] =
            make_float2((vb[nt][0] - mb) * ib * gg.x + bb.x,
                        (vb[nt][1] - mb) * ib * gg.y + bb.y);
    }
}

// ======= flash attention, tf32 MMA, Q-frag hoist + double-buffered K/V =======
#define TSTR 68
__global__ void flash_attn_tc(const float* __restrict__ q, const float* __restrict__ k,
                              const float* __restrict__ v, float* __restrict__ o)
{
    extern __shared__ float fsm[];
    // regions of 64*TSTR floats: 0=Qs, 1=Ks0, 2=Ks1, 3=Vs0, 4=Vs1, 5=Ss
    float* Qs = fsm;
    float* Ss = fsm + 5 * 64 * TSTR;
    float* alpha_s = fsm + 6 * 64 * TSTR;
    float* l_s     = alpha_s + 64;
    u32* QsU = (u32*)Qs; u32* SsU = (u32*)Ss;

    int tid  = threadIdx.x;
    int wid  = tid >> 5, lane = tid & 31;
    int g    = lane >> 2, tig = lane & 3;
    int wm   = wid & 3, wn = wid >> 2;
    int r0   = wm * 16, n0 = wn * 32;
    int qrow0 = blockIdx.x * 64;
    int hcol  = blockIdx.y * DH;

    #pragma unroll
    for (int i = 0; i < 16; i++) {
        int idx = tid + i * 256;
        int r = idx >> 6, d = idx & 63;
        QsU[r * TSTR + d] = f2tf32(q[(size_t)(qrow0 + r) * D + hcol + d]);
    }

    float kreg[16], vreg[16];
    #pragma unroll
    for (int i = 0; i < 16; i++) {
        int idx = tid + i * 256;
        int c = idx >> 6, d = idx & 63;
        kreg[i] = k[(size_t)c * D + hcol + d];
        vreg[i] = v[(size_t)c * D + hcol + d];
    }
    __syncthreads();

    // hoist Q fragments (loop-invariant)
    u32 qa[8][4];
    #pragma unroll
    for (int ks = 0; ks < 8; ks++) {
        int k0 = ks * 8;
        qa[ks][0] = QsU[(r0 + g) * TSTR + k0 + tig];
        qa[ks][1] = QsU[(r0 + g + 8) * TSTR + k0 + tig];
        qa[ks][2] = QsU[(r0 + g) * TSTR + k0 + tig + 4];
        qa[ks][3] = QsU[(r0 + g + 8) * TSTR + k0 + tig + 4];
    }

    int sr = tid >> 2, sc = (tid & 3) * 16;
    float m_i = -1e30f, l_i = 0.0f;
    const float scale = 0.125f;
    float of[4][4] = {};
    int p = 0;

    for (int kb = 0; kb < N; kb += 64) {
        u32* KsU = (u32*)(fsm + (1 + p) * 64 * TSTR);
        u32* VsU = (u32*)(fsm + (3 + p) * 64 * TSTR);
        #pragma unroll
        for (int i = 0; i < 16; i++) {
            int idx = tid + i * 256;
            int c = idx >> 6, d = idx & 63;
            KsU[c * TSTR + d] = f2tf32(kreg[i]);
            VsU[d * TSTR + c] = f2tf32(vreg[i]);
        }
        __syncthreads();
        if (kb + 64 < N) {
            #pragma unroll
            for (int i = 0; i < 16; i++) {
                int idx = tid + i * 256;
                int c = idx >> 6, d = idx & 63;
                kreg[i] = k[(size_t)(kb + 64 + c) * D + hcol + d];
                vreg[i] = v[(size_t)(kb + 64 + c) * D + hcol + d];
            }
        }

        // S = Q @ K^T
        {
            float sf[4][4] = {};
            #pragma unroll
            for (int ks = 0; ks < 8; ks++) {
                int k0 = ks * 8;
                #pragma unroll
                for (int nt = 0; nt < 4; nt++) {
                    int n = n0 + nt * 8;
                    u32 b0 = KsU[(n + g) * TSTR + k0 + tig];
                    u32 b1 = KsU[(n + g) * TSTR + k0 + tig + 4];
                    mma_tf32(sf[nt][0], sf[nt][1], sf[nt][2], sf[nt][3],
                             qa[ks][0], qa[ks][1], qa[ks][2], qa[ks][3], b0, b1);
                }
            }
            #pragma unroll
            for (int nt = 0; nt < 4; nt++) {
                int n = n0 + nt * 8 + 2 * tig;
                *(float2*)&Ss[(r0 + g) * TSTR + n]     = make_float2(sf[nt][0], sf[nt][1]);
                *(float2*)&Ss[(r0 + g + 8) * TSTR + n] = make_float2(sf[nt][2], sf[nt][3]);
            }
        }
        __syncthreads();

        // softmax: 4 threads per row, 16 cols each
        {
            float4 x0 = *(float4*)&Ss[sr * TSTR + sc + 0];
            float4 x1 = *(float4*)&Ss[sr * TSTR + sc + 4];
            float4 x2 = *(float4*)&Ss[sr * TSTR + sc + 8];
            float4 x3 = *(float4*)&Ss[sr * TSTR + sc + 12];
            float xs[16] = {x0.x,x0.y,x0.z,x0.w, x1.x,x1.y,x1.z,x1.w,
                            x2.x,x2.y,x2.z,x2.w, x3.x,x3.y,x3.z,x3.w};
            float mt = -1e30f;
            #pragma unroll
            for (int i = 0; i < 16; i++) { xs[i] *= scale; mt = fmaxf(mt, xs[i]); }
            mt = fmaxf(mt, __shfl_xor_sync(0xffffffffu, mt, 1));
            mt = fmaxf(mt, __shfl_xor_sync(0xffffffffu, mt, 2));
            float mnew = fmaxf(m_i, mt);
            float lt = 0.0f;
            #pragma unroll
            for (int i = 0; i < 16; i++) { xs[i] = __expf(xs[i] - mnew); lt += xs[i]; }
            lt += __shfl_xor_sync(0xffffffffu, lt, 1);
            lt += __shfl_xor_sync(0xffffffffu, lt, 2);
            float alpha = __expf(m_i - mnew);
            l_i = l_i * alpha + lt;
            m_i = mnew;
            if ((tid & 3) == 0) alpha_s[sr] = alpha;
            #pragma unroll
            for (int c4 = 0; c4 < 4; c4++) {
                uint4 pb = make_uint4(f2tf32(xs[c4*4+0]), f2tf32(xs[c4*4+1]),
                                      f2tf32(xs[c4*4+2]), f2tf32(xs[c4*4+3]));
                *(uint4*)&SsU[sr * TSTR + sc + c4 * 4] = pb;
            }
        }
        __syncthreads();

        // O = alpha*O + P @ V
        {
            float af  = alpha_s[r0 + g];
            float af8 = alpha_s[r0 + g + 8];
            #pragma unroll
            for (int nt = 0; nt < 4; nt++) {
                of[nt][0] *= af;  of[nt][1] *= af;
                of[nt][2] *= af8; of[nt][3] *= af8;
            }
            #pragma unroll
            for (int ks = 0; ks < 8; ks++) {
                int k0 = ks * 8;
                u32 a0 = SsU[(r0 + g) * TSTR + k0 + tig];
                u32 a1 = SsU[(r0 + g + 8) * TSTR + k0 + tig];
                u32 a2 = SsU[(r0 + g) * TSTR + k0 + tig + 4];
                u32 a3 = SsU[(r0 + g + 8) * TSTR + k0 + tig + 4];
                #pragma unroll
                for (int nt = 0; nt < 4; nt++) {
                    int n = n0 + nt * 8;
                    u32 b0 = VsU[(n + g) * TSTR + k0 + tig];
                    u32 b1 = VsU[(n + g) * TSTR + k0 + tig + 4];
                    mma_tf32(of[nt][0], of[nt][1], of[nt][2], of[nt][3],
                             a0, a1, a2, a3, b0, b1);
                }
            }
        }
        p ^= 1;
    }

    __syncthreads();
    if ((tid & 3) == 0) l_s[sr] = l_i;
    __syncthreads();
    float linv  = 1.0f / l_s[r0 + g];
    float linv8 = 1.0f / l_s[r0 + g + 8];
    #pragma unroll
    for (int nt = 0; nt < 4; nt++) {
        int n = hcol + n0 + nt * 8 + 2 * tig;
        int ra = qrow0 + r0 + g, rb = qrow0 + r0 + g + 8;
        *(float2*)&o[(size_t)ra * D + n] = make_float2(of[nt][0] * linv,  of[nt][1] * linv);
        *(float2*)&o[(size_t)rb * D + n] = make_float2(of[nt][2] * linv8, of[nt][3] * linv8);
    }
}

// ---------------- hypergraph conv pieces ----------------
__global__ void zero_kernel(float* p, int n)
{
    int i = blockIdx.x * blockDim.x + threadIdx.x;
    if (i < n) p[i] = 0.0f;
}

__global__ void degree_kernel(const void* __restrict__ edge,
                              float* __restrict__ bdeg, float* __restrict__ ddeg)
{
    int i = blockIdx.x * blockDim.x + threadIdx.x;
    if (i < NNZ) {
        int2 ne = load_edge(edge, i);
        if ((unsigned)ne.x < N && (unsigned)ne.y < NE) {
            atomicAdd(&ddeg[ne.x], 1.0f);
            atomicAdd(&bdeg[ne.y], 1.0f);
        }
    }
}

__global__ void scatter_node_to_edge(const void* __restrict__ edge,
                                     const float* __restrict__ xt, float* __restrict__ e)
{
    int i = blockIdx.x * blockDim.x + threadIdx.x;   // NNZ*32 threads
    int nz = i >> 5, lane = i & 31;
    int2 ne = load_edge(edge, nz);
    if ((unsigned)ne.x >= N || (unsigned)ne.y >= NE) return;
    float4 p = *(const float4*)&xt[(size_t)ne.x * D + lane * 4];
    float* dst = &e[(size_t)ne.y * D + lane * 4];
    atomicAdd(dst + 0, p.x);
    atomicAdd(dst + 1, p.y);
    atomicAdd(dst + 2, p.z);
    atomicAdd(dst + 3, p.w);
}

__global__ void scatter_edge_to_node(const void* __restrict__ edge,
                                     const float* __restrict__ e,
                                     const float* __restrict__ bdeg,
                                     float* __restrict__ out)
{
    int i = blockIdx.x * blockDim.x + threadIdx.x;   // NNZ*32 threads
    int nz = i >> 5, lane = i & 31;
    int2 ne = load_edge(edge, nz);
    if ((unsigned)ne.x >= N || (unsigned)ne.y >= NE) return;
    float bd = bdeg[ne.y];
    float bi = (bd > 0.0f) ? (1.0f / bd) : 0.0f;
    float4 p = *(const float4*)&e[(size_t)ne.y * D + lane * 4];
    float* dst = &out[(size_t)ne.x * D + lane * 4];
    atomicAdd(dst + 0, p.x * bi);
    atomicAdd(dst + 1, p.y * bi);
    atomicAdd(dst + 2, p.z * bi);
    atomicAdd(dst + 3, p.w * bi);
}

__global__ void finalize_kernel(float* __restrict__ out, const float* __restrict__ ddeg,
                                const float* __restrict__ bh)
{
    int i = blockIdx.x * blockDim.x + threadIdx.x;  // over N*D
    int row = i >> 7, d = i & 127;
    float dd = ddeg[row];
    float v = out[i] * ((dd > 0.0f) ? (1.0f / dd) : 0.0f) + bh[d];
    out[i] = fmaxf(v, 0.0f);
}

// ---------------- launch ----------------
extern "C" void kernel_launch(void* const* d_in, const int* in_sizes, int n_in,
                              void* d_out, int out_size)
{
    const float* x    = (const float*)d_in[0];
    const void*  edge = d_in[1];
    const float* Wq = (const float*)d_in[2],  *bq  = (const float*)d_in[3];
    const float* Wk = (const float*)d_in[4],  *bk  = (const float*)d_in[5];
    const float* Wv = (const float*)d_in[6],  *bv  = (const float*)d_in[7];
    const float* Wo = (const float*)d_in[8],  *bo  = (const float*)d_in[9];
    const float* g1 = (const float*)d_in[10], *b1  = (const float*)d_in[11];
    const float* W1 = (const float*)d_in[12], *bf1 = (const float*)d_in[13];
    const float* W2 = (const float*)d_in[14], *bf2 = (const float*)d_in[15];
    const float* g2 = (const float*)d_in[16], *b2  = (const float*)d_in[17];
    const float* Wh = (const float*)d_in[18], *bh  = (const float*)d_in[19];
    float* out = (float*)d_out;

    float *h, *q, *k, *v, *o, *z, *e, *bdeg, *ddeg;
    cudaGetSymbolAddress((void**)&h, g_h);
    cudaGetSymbolAddress((void**)&q, g_q);
    cudaGetSymbolAddress((void**)&k, g_k);
    cudaGetSymbolAddress((void**)&v, g_v);
    cudaGetSymbolAddress((void**)&o, g_o);
    cudaGetSymbolAddress((void**)&z, g_z);
    cudaGetSymbolAddress((void**)&e, g_e);
    cudaGetSymbolAddress((void**)&bdeg, g_bdeg);
    cudaGetSymbolAddress((void**)&ddeg, g_ddeg);

    const int FSMEM = (6 * 64 * TSTR + 128) * (int)sizeof(float);  // ~105 KB
    cudaFuncSetAttribute(flash_attn_tc, cudaFuncAttributeMaxDynamicSharedMemorySize, FSMEM);

    detect_edge_kernel<<<1, 32>>>((const int*)edge);

    dim3 gD(D / 64, N / 64);       // 2 x 64
    dim3 gF(FF / 64, N / 64);      // 4 x 64
    dim3 gQKV(D / 64, N / 64, 3);  // 2 x 64 x 3

    for (int it = 0; it < 2; ++it) {
        const float* hin = (it == 0) ? x : h;
        qkv_gemm_tc<<<gQKV, 256>>>(hin, Wq, bq, Wk, bk, Wv, bv, q, k, v);
        flash_attn_tc<<<dim3(N / 64, H), 256, FSMEM>>>(q, k, v, o);
        gemm_ln_tc<<<N / 64, 256>>>(o, Wo, bo, hin, g1, b1, h, D);
        gemm_tc<<<gF, 256>>>(h, W1, bf1, z, FF, D, 1);
        gemm_ln_tc<<<N / 64, 256>>>(z, W2, bf2, h, g2, b2, h, FF);
    }

    // xt = h @ Wh (reuse q buffer)
    gemm_tc<<<gD, 256>>>(h, Wh, nullptr, q, D, D, 0);

    zero_kernel<<<(NE * D + 255) / 256, 256>>>(e, NE * D);
    zero_kernel<<<(NE + 255) / 256, 256>>>(bdeg, NE);
    zero_kernel<<<(N + 255) / 256, 256>>>(ddeg, N);
    zero_kernel<<<(N * D + 255) / 256, 256>>>(out, N * D);

    degree_kernel<<<NNZ / 256, 256>>>(edge, bdeg, ddeg);
    scatter_node_to_edge<<<(NNZ * 32) / 256, 256>>>(edge, q, e);
    scatter_edge_to_node<<<(NNZ * 32) / 256, 256>>>(edge, e, bdeg, out);
    finalize_kernel<<<(N * D) / 256, 256>>>(out, ddeg, bh);
}

// round 13
// speedup vs baseline: 2.7024x; 1.0783x over previous
#include <cuda_runtime.h>
#include <cuda_bf16.h>
#include <math.h>

#define N   4096
#define D   128
#define H   2
#define DH  64
#define FF  256
#define NE  2048
#define NNZ 65536
#define EPS 1e-5f

typedef unsigned long long u64;
typedef unsigned int u32;

// ---------------- tf32 helpers ----------------
__device__ __forceinline__ u32 f2tf32(float x) {
    u32 r; asm("cvt.rna.tf32.f32 %0, %1;" : "=r"(r) : "f"(x)); return r;
}
__device__ __forceinline__ void mma_tf32(float& d0, float& d1, float& d2, float& d3,
                                         u32 a0, u32 a1, u32 a2, u32 a3,
                                         u32 b0, u32 b1)
{
    asm("mma.sync.aligned.m16n8k8.row.col.f32.tf32.tf32.f32 "
        "{%0,%1,%2,%3},{%4,%5,%6,%7},{%8,%9},{%0,%1,%2,%3};"
        : "+f"(d0), "+f"(d1), "+f"(d2), "+f"(d3)
        : "r"(a0), "r"(a1), "r"(a2), "r"(a3), "r"(b0), "r"(b1));
}

// ---------------- scratch (no allocation allowed) ----------------
__device__ float g_h[N * D];
__device__ float g_q[N * D];
__device__ float g_k[N * D];
__device__ float g_v[N * D];
__device__ float g_o[N * D];
__device__ float g_z[N * FF];
__device__ float g_e[NE * D];
__device__ int   g_edge_is64;
// CSR scratch
__device__ int g_cnt_e[NE], g_cnt_n[N];
__device__ int g_start_e[NE], g_start_n[N];
__device__ int g_cur_e[NE], g_cur_n[N];
__device__ int g_bucket_e[NNZ];   // node indices grouped by hyperedge
__device__ int g_bucket_n[NNZ];   // hyperedge indices grouped by node

// ---------------- edge dtype detection ----------------
__global__ void detect_edge_kernel(const int* __restrict__ e32)
{
    if (threadIdx.x == 0 && blockIdx.x == 0) {
        int is64 = 1;
        #pragma unroll
        for (int i = 1; i < 64; i += 2)
            if (e32[i] != 0) is64 = 0;
        g_edge_is64 = is64;
    }
}

__device__ __forceinline__ int2 load_edge(const void* __restrict__ edge, int nz)
{
    if (g_edge_is64) {
        const long long* e = (const long long*)edge;
        return make_int2((int)e[nz], (int)e[NNZ + nz]);
    } else {
        const int* e = (const int*)edge;
        return make_int2(e[nz], e[NNZ + nz]);
    }
}

// ======= tf32 tensor-core GEMM: C = act(A @ B + bias), 64x64 tile, KC=32 =======
#define GSTR 36
struct GemmTcSmem { u32 As[64 * GSTR]; u32 Bs[64 * GSTR]; };

__device__ __forceinline__ void gemm_tile_tc(const float* __restrict__ A,
                                             const float* __restrict__ B,
                                             const float* __restrict__ bias,
                                             float* __restrict__ C,
                                             int Nc, int K, int act,
                                             int row0, int col0, GemmTcSmem& sm)
{
    int tid = threadIdx.x;
    int wid = tid >> 5, lane = tid & 31;
    int g = lane >> 2, tig = lane & 3;
    int wm = wid & 3, wn = wid >> 2;
    int r0 = wm * 16, n0 = wn * 32;

    float areg[8], breg[8];
    #pragma unroll
    for (int i = 0; i < 8; i++) {
        int idx = tid + i * 256;
        int am = idx >> 5, ak = idx & 31;
        areg[i] = A[(size_t)(row0 + am) * K + ak];
        int bk = idx >> 6, bn = idx & 63;
        breg[i] = B[(size_t)bk * Nc + col0 + bn];
    }

    float acc[4][4] = {};
    for (int k0 = 0; k0 < K; k0 += 32) {
        __syncthreads();
        #pragma unroll
        for (int i = 0; i < 8; i++) {
            int idx = tid + i * 256;
            int am = idx >> 5, ak = idx & 31;
            sm.As[am * GSTR + ak] = f2tf32(areg[i]);
            int bk = idx >> 6, bn = idx & 63;
            sm.Bs[bn * GSTR + bk] = f2tf32(breg[i]);
        }
        __syncthreads();
        if (k0 + 32 < K) {
            #pragma unroll
            for (int i = 0; i < 8; i++) {
                int idx = tid + i * 256;
                int am = idx >> 5, ak = idx & 31;
                areg[i] = A[(size_t)(row0 + am) * K + (k0 + 32) + ak];
                int bk = idx >> 6, bn = idx & 63;
                breg[i] = B[(size_t)(k0 + 32 + bk) * Nc + col0 + bn];
            }
        }
        #pragma unroll
        for (int ks = 0; ks < 4; ks++) {
            int kk = ks * 8;
            u32 a0 = sm.As[(r0 + g) * GSTR + kk + tig];
            u32 a1 = sm.As[(r0 + g + 8) * GSTR + kk + tig];
            u32 a2 = sm.As[(r0 + g) * GSTR + kk + tig + 4];
            u32 a3 = sm.As[(r0 + g + 8) * GSTR + kk + tig + 4];
            #pragma unroll
            for (int nt = 0; nt < 4; nt++) {
                int n = n0 + nt * 8;
                u32 b0 = sm.Bs[(n + g) * GSTR + kk + tig];
                u32 b1 = sm.Bs[(n + g) * GSTR + kk + tig + 4];
                mma_tf32(acc[nt][0], acc[nt][1], acc[nt][2], acc[nt][3],
                         a0, a1, a2, a3, b0, b1);
            }
        }
    }

    int ra = row0 + r0 + g, rb = ra + 8;
    #pragma unroll
    for (int nt = 0; nt < 4; nt++) {
        int c = col0 + n0 + nt * 8 + 2 * tig;
        float bc0 = bias ? bias[c] : 0.0f;
        float bc1 = bias ? bias[c + 1] : 0.0f;
        float v0 = acc[nt][0] + bc0, v1 = acc[nt][1] + bc1;
        float v2 = acc[nt][2] + bc0, v3 = acc[nt][3] + bc1;
        if (act == 1) {
            v0 = 1.0f / (1.0f + __expf(-v0));
            v1 = 1.0f / (1.0f + __expf(-v1));
            v2 = 1.0f / (1.0f + __expf(-v2));
            v3 = 1.0f / (1.0f + __expf(-v3));
        }
        *(float2*)&C[(size_t)ra * Nc + c] = make_float2(v0, v1);
        *(float2*)&C[(size_t)rb * Nc + c] = make_float2(v2, v3);
    }
}

__global__ void gemm_tc(const float* __restrict__ A, const float* __restrict__ B,
                        const float* __restrict__ bias, float* __restrict__ C,
                        int Nc, int K, int act)
{
    __shared__ GemmTcSmem sm;
    gemm_tile_tc(A, B, bias, C, Nc, K, act, blockIdx.y * 64, blockIdx.x * 64, sm);
}

__global__ void qkv_gemm_tc(const float* __restrict__ A,
                            const float* __restrict__ Wq, const float* __restrict__ bq,
                            const float* __restrict__ Wk, const float* __restrict__ bk,
                            const float* __restrict__ Wv, const float* __restrict__ bv,
                            float* __restrict__ q, float* __restrict__ k, float* __restrict__ v)
{
    __shared__ GemmTcSmem sm;
    const float* B; const float* bias; float* C;
    if (blockIdx.z == 0)      { B = Wq; bias = bq; C = q; }
    else if (blockIdx.z == 1) { B = Wk; bias = bk; C = k; }
    else                      { B = Wv; bias = bv; C = v; }
    gemm_tile_tc(A, B, bias, C, D, D, 0, blockIdx.y * 64, blockIdx.x * 64, sm);
}

// ======= fused GEMM + residual + LayerNorm: C = LN(hin + A@B + bias) =======
// Tile 32 rows x 128 cols (full D) -> grid = N/32 = 128 CTAs.
// 256 threads, 8 warps 2(m) x 4(n), warp tile 16 x 32.
struct GemmLnSmem {
    u32 As[32 * GSTR];
    u32 Bs[128 * GSTR];
    float ps[32 * 4];   // row partial sums   [row][wn]
    float pq[32 * 4];   // row partial sumsq  [row][wn]
};

__global__ void gemm_ln_tc(const float* __restrict__ A, const float* __restrict__ B,
                           const float* __restrict__ bias, const float* __restrict__ hin,
                           const float* __restrict__ lng, const float* __restrict__ lnb,
                           float* __restrict__ C, int K)
{
    __shared__ GemmLnSmem sm;
    int tid = threadIdx.x;
    int wid = tid >> 5, lane = tid & 31;
    int gq = lane >> 2, tig = lane & 3;
    int wm = wid & 1, wn = wid >> 1;     // 2 x 4
    int r0 = wm * 16, n0 = wn * 32;
    int row0 = blockIdx.x * 32;

    float areg[4], breg[16];
    #pragma unroll
    for (int i = 0; i < 4; i++) {
        int idx = tid + i * 256;
        int am = idx >> 5, ak = idx & 31;
        areg[i] = A[(size_t)(row0 + am) * K + ak];
    }
    #pragma unroll
    for (int i = 0; i < 16; i++) {
        int idx = tid + i * 256;
        int bk = idx >> 7, bn = idx & 127;
        breg[i] = B[(size_t)bk * D + bn];
    }

    float acc[4][4] = {};
    for (int k0 = 0; k0 < K; k0 += 32) {
        __syncthreads();
        #pragma unroll
        for (int i = 0; i < 4; i++) {
            int idx = tid + i * 256;
            int am = idx >> 5, ak = idx & 31;
            sm.As[am * GSTR + ak] = f2tf32(areg[i]);
        }
        #pragma unroll
        for (int i = 0; i < 16; i++) {
            int idx = tid + i * 256;
            int bk = idx >> 7, bn = idx & 127;
            sm.Bs[bn * GSTR + bk] = f2tf32(breg[i]);
        }
        __syncthreads();
        if (k0 + 32 < K) {
            #pragma unroll
            for (int i = 0; i < 4; i++) {
                int idx = tid + i * 256;
                int am = idx >> 5, ak = idx & 31;
                areg[i] = A[(size_t)(row0 + am) * K + (k0 + 32) + ak];
            }
            #pragma unroll
            for (int i = 0; i < 16; i++) {
                int idx = tid + i * 256;
                int bk = idx >> 7, bn = idx & 127;
                breg[i] = B[(size_t)(k0 + 32 + bk) * D + bn];
            }
        }
        #pragma unroll
        for (int ks = 0; ks < 4; ks++) {
            int kk = ks * 8;
            u32 a0 = sm.As[(r0 + gq) * GSTR + kk + tig];
            u32 a1 = sm.As[(r0 + gq + 8) * GSTR + kk + tig];
            u32 a2 = sm.As[(r0 + gq) * GSTR + kk + tig + 4];
            u32 a3 = sm.As[(r0 + gq + 8) * GSTR + kk + tig + 4];
            #pragma unroll
            for (int nt = 0; nt < 4; nt++) {
                int n = n0 + nt * 8;
                u32 b0 = sm.Bs[(n + gq) * GSTR + kk + tig];
                u32 b1 = sm.Bs[(n + gq) * GSTR + kk + tig + 4];
                mma_tf32(acc[nt][0], acc[nt][1], acc[nt][2], acc[nt][3],
                         a0, a1, a2, a3, b0, b1);
            }
        }
    }

    // epilogue: residual + bias, LN stats (quad shfl + 4-way smem partials)
    int ra = row0 + r0 + gq, rb = ra + 8;
    float va[4][2], vb[4][2];
    float sa = 0.0f, qa = 0.0f, sb = 0.0f, qb = 0.0f;
    #pragma unroll
    for (int nt = 0; nt < 4; nt++) {
        int c = n0 + nt * 8 + 2 * tig;
        float2 bc  = *(const float2*)&bias[c];
        float2 ha  = *(const float2*)&hin[(size_t)ra * D + c];
        float2 hb  = *(const float2*)&hin[(size_t)rb * D + c];
        va[nt][0] = acc[nt][0] + bc.x + ha.x;
        va[nt][1] = acc[nt][1] + bc.y + ha.y;
        vb[nt][0] = acc[nt][2] + bc.x + hb.x;
        vb[nt][1] = acc[nt][3] + bc.y + hb.y;
        sa += va[nt][0] + va[nt][1];
        qa += va[nt][0] * va[nt][0] + va[nt][1] * va[nt][1];
        sb += vb[nt][0] + vb[nt][1];
        qb += vb[nt][0] * vb[nt][0] + vb[nt][1] * vb[nt][1];
    }
    #pragma unroll
    for (int off = 1; off <= 2; off <<= 1) {
        sa += __shfl_xor_sync(0xffffffffu, sa, off);
        qa += __shfl_xor_sync(0xffffffffu, qa, off);
        sb += __shfl_xor_sync(0xffffffffu, sb, off);
        qb += __shfl_xor_sync(0xffffffffu, qb, off);
    }
    if (tig == 0) {
        sm.ps[(r0 + gq) * 4 + wn] = sa;     sm.pq[(r0 + gq) * 4 + wn] = qa;
        sm.ps[(r0 + gq + 8) * 4 + wn] = sb; sm.pq[(r0 + gq + 8) * 4 + wn] = qb;
    }
    __syncthreads();
    int ia4 = (r0 + gq) * 4, ib4 = (r0 + gq + 8) * 4;
    float Sa = sm.ps[ia4] + sm.ps[ia4 + 1] + sm.ps[ia4 + 2] + sm.ps[ia4 + 3];
    float Qa = sm.pq[ia4] + sm.pq[ia4 + 1] + sm.pq[ia4 + 2] + sm.pq[ia4 + 3];
    float Sb = sm.ps[ib4] + sm.ps[ib4 + 1] + sm.ps[ib4 + 2] + sm.ps[ib4 + 3];
    float Qb = sm.pq[ib4] + sm.pq[ib4 + 1] + sm.pq[ib4 + 2] + sm.pq[ib4 + 3];
    float ma = Sa * (1.0f / D), vva = Qa * (1.0f / D) - ma * ma;
    float mb = Sb * (1.0f / D), vvb = Qb * (1.0f / D) - mb * mb;
    float ia = rsqrtf(vva + EPS), ib = rsqrtf(vvb + EPS);
    #pragma unroll
    for (int nt = 0; nt < 4; nt++) {
        int c = n0 + nt * 8 + 2 * tig;
        float2 gg = *(const float2*)&lng[c];
        float2 bb = *(const float2*)&lnb[c];
        *(float2*)&C[(size_t)ra * D + c] =
            make_float2((va[nt][0] - ma) * ia * gg.x + bb.x,
                        (va[nt][1] - ma) * ia * gg.y + bb.y);
        *(float2*)&C[(size_t)rb * D + c] =
            make_float2((vb[nt][0] - mb) * ib * gg.x + bb.x,
                        (vb[nt][1] - mb) * ib * gg.y + bb.y);
    }
}

// ======= flash attention, tf32 MMA, Q-frag hoist + double-buffered K/V =======
#define TSTR 68
__global__ void flash_attn_tc(const float* __restrict__ q, const float* __restrict__ k,
                              const float* __restrict__ v, float* __restrict__ o)
{
    extern __shared__ float fsm[];
    float* Qs = fsm;
    float* Ss = fsm + 5 * 64 * TSTR;
    float* alpha_s = fsm + 6 * 64 * TSTR;
    float* l_s     = alpha_s + 64;
    u32* QsU = (u32*)Qs; u32* SsU = (u32*)Ss;

    int tid  = threadIdx.x;
    int wid  = tid >> 5, lane = tid & 31;
    int g    = lane >> 2, tig = lane & 3;
    int wm   = wid & 3, wn = wid >> 2;
    int r0   = wm * 16, n0 = wn * 32;
    int qrow0 = blockIdx.x * 64;
    int hcol  = blockIdx.y * DH;

    #pragma unroll
    for (int i = 0; i < 16; i++) {
        int idx = tid + i * 256;
        int r = idx >> 6, d = idx & 63;
        QsU[r * TSTR + d] = f2tf32(q[(size_t)(qrow0 + r) * D + hcol + d]);
    }

    float kreg[16], vreg[16];
    #pragma unroll
    for (int i = 0; i < 16; i++) {
        int idx = tid + i * 256;
        int c = idx >> 6, d = idx & 63;
        kreg[i] = k[(size_t)c * D + hcol + d];
        vreg[i] = v[(size_t)c * D + hcol + d];
    }
    __syncthreads();

    u32 qa[8][4];
    #pragma unroll
    for (int ks = 0; ks < 8; ks++) {
        int k0 = ks * 8;
        qa[ks][0] = QsU[(r0 + g) * TSTR + k0 + tig];
        qa[ks][1] = QsU[(r0 + g + 8) * TSTR + k0 + tig];
        qa[ks][2] = QsU[(r0 + g) * TSTR + k0 + tig + 4];
        qa[ks][3] = QsU[(r0 + g + 8) * TSTR + k0 + tig + 4];
    }

    int sr = tid >> 2, sc = (tid & 3) * 16;
    float m_i = -1e30f, l_i = 0.0f;
    const float scale = 0.125f;
    float of[4][4] = {};
    int p = 0;

    for (int kb = 0; kb < N; kb += 64) {
        u32* KsU = (u32*)(fsm + (1 + p) * 64 * TSTR);
        u32* VsU = (u32*)(fsm + (3 + p) * 64 * TSTR);
        #pragma unroll
        for (int i = 0; i < 16; i++) {
            int idx = tid + i * 256;
            int c = idx >> 6, d = idx & 63;
            KsU[c * TSTR + d] = f2tf32(kreg[i]);
            VsU[d * TSTR + c] = f2tf32(vreg[i]);
        }
        __syncthreads();
        if (kb + 64 < N) {
            #pragma unroll
            for (int i = 0; i < 16; i++) {
                int idx = tid + i * 256;
                int c = idx >> 6, d = idx & 63;
                kreg[i] = k[(size_t)(kb + 64 + c) * D + hcol + d];
                vreg[i] = v[(size_t)(kb + 64 + c) * D + hcol + d];
            }
        }

        // S = Q @ K^T
        {
            float sf[4][4] = {};
            #pragma unroll
            for (int ks = 0; ks < 8; ks++) {
                int k0 = ks * 8;
                #pragma unroll
                for (int nt = 0; nt < 4; nt++) {
                    int n = n0 + nt * 8;
                    u32 b0 = KsU[(n + g) * TSTR + k0 + tig];
                    u32 b1 = KsU[(n + g) * TSTR + k0 + tig + 4];
                    mma_tf32(sf[nt][0], sf[nt][1], sf[nt][2], sf[nt][3],
                             qa[ks][0], qa[ks][1], qa[ks][2], qa[ks][3], b0, b1);
                }
            }
            #pragma unroll
            for (int nt = 0; nt < 4; nt++) {
                int n = n0 + nt * 8 + 2 * tig;
                *(float2*)&Ss[(r0 + g) * TSTR + n]     = make_float2(sf[nt][0], sf[nt][1]);
                *(float2*)&Ss[(r0 + g + 8) * TSTR + n] = make_float2(sf[nt][2], sf[nt][3]);
            }
        }
        __syncthreads();

        // softmax
        {
            float4 x0 = *(float4*)&Ss[sr * TSTR + sc + 0];
            float4 x1 = *(float4*)&Ss[sr * TSTR + sc + 4];
            float4 x2 = *(float4*)&Ss[sr * TSTR + sc + 8];
            float4 x3 = *(float4*)&Ss[sr * TSTR + sc + 12];
            float xs[16] = {x0.x,x0.y,x0.z,x0.w, x1.x,x1.y,x1.z,x1.w,
                            x2.x,x2.y,x2.z,x2.w, x3.x,x3.y,x3.z,x3.w};
            float mt = -1e30f;
            #pragma unroll
            for (int i = 0; i < 16; i++) { xs[i] *= scale; mt = fmaxf(mt, xs[i]); }
            mt = fmaxf(mt, __shfl_xor_sync(0xffffffffu, mt, 1));
            mt = fmaxf(mt, __shfl_xor_sync(0xffffffffu, mt, 2));
            float mnew = fmaxf(m_i, mt);
            float lt = 0.0f;
            #pragma unroll
            for (int i = 0; i < 16; i++) { xs[i] = __expf(xs[i] - mnew); lt += xs[i]; }
            lt += __shfl_xor_sync(0xffffffffu, lt, 1);
            lt += __shfl_xor_sync(0xffffffffu, lt, 2);
            float alpha = __expf(m_i - mnew);
            l_i = l_i * alpha + lt;
            m_i = mnew;
            if ((tid & 3) == 0) alpha_s[sr] = alpha;
            #pragma unroll
            for (int c4 = 0; c4 < 4; c4++) {
                uint4 pb = make_uint4(f2tf32(xs[c4*4+0]), f2tf32(xs[c4*4+1]),
                                      f2tf32(xs[c4*4+2]), f2tf32(xs[c4*4+3]));
                *(uint4*)&SsU[sr * TSTR + sc + c4 * 4] = pb;
            }
        }
        __syncthreads();

        // O = alpha*O + P @ V
        {
            float af  = alpha_s[r0 + g];
            float af8 = alpha_s[r0 + g + 8];
            #pragma unroll
            for (int nt = 0; nt < 4; nt++) {
                of[nt][0] *= af;  of[nt][1] *= af;
                of[nt][2] *= af8; of[nt][3] *= af8;
            }
            #pragma unroll
            for (int ks = 0; ks < 8; ks++) {
                int k0 = ks * 8;
                u32 a0 = SsU[(r0 + g) * TSTR + k0 + tig];
                u32 a1 = SsU[(r0 + g + 8) * TSTR + k0 + tig];
                u32 a2 = SsU[(r0 + g) * TSTR + k0 + tig + 4];
                u32 a3 = SsU[(r0 + g + 8) * TSTR + k0 + tig + 4];
                #pragma unroll
                for (int nt = 0; nt < 4; nt++) {
                    int n = n0 + nt * 8;
                    u32 b0 = VsU[(n + g) * TSTR + k0 + tig];
                    u32 b1 = VsU[(n + g) * TSTR + k0 + tig + 4];
                    mma_tf32(of[nt][0], of[nt][1], of[nt][2], of[nt][3],
                             a0, a1, a2, a3, b0, b1);
                }
            }
        }
        p ^= 1;
    }

    __syncthreads();
    if ((tid & 3) == 0) l_s[sr] = l_i;
    __syncthreads();
    float linv  = 1.0f / l_s[r0 + g];
    float linv8 = 1.0f / l_s[r0 + g + 8];
    #pragma unroll
    for (int nt = 0; nt < 4; nt++) {
        int n = hcol + n0 + nt * 8 + 2 * tig;
        int ra = qrow0 + r0 + g, rb = qrow0 + r0 + g + 8;
        *(float2*)&o[(size_t)ra * D + n] = make_float2(of[nt][0] * linv,  of[nt][1] * linv);
        *(float2*)&o[(size_t)rb * D + n] = make_float2(of[nt][2] * linv8, of[nt][3] * linv8);
    }
}

// ======= hypergraph conv via CSR build + gather (no float atomics) =======
__global__ void zero_counts_kernel()
{
    int i = blockIdx.x * blockDim.x + threadIdx.x;
    if (i < NE) g_cnt_e[i] = 0;
    if (i < N)  g_cnt_n[i] = 0;
}

__global__ void count_kernel(const void* __restrict__ edge)
{
    int i = blockIdx.x * blockDim.x + threadIdx.x;
    if (i < NNZ) {
        int2 ne = load_edge(edge, i);
        if ((unsigned)ne.x < N && (unsigned)ne.y < NE) {
            atomicAdd(&g_cnt_n[ne.x], 1);
            atomicAdd(&g_cnt_e[ne.y], 1);
        }
    }
}

// exclusive scan of cnt[0..n) into start & cur; n/1024 elems per thread (<=4)
__device__ void block_scan_excl(const int* cnt, int* start, int* cur, int n, int* smbuf)
{
    int tid = threadIdx.x;               // 1024 threads
    int per = n >> 10;
    int base = tid * per;
    int vals[4];
    int local = 0;
    for (int i = 0; i < per; i++) { vals[i] = cnt[base + i]; local += vals[i]; }
    int lane = tid & 31, warp = tid >> 5;
    int x = local;
    #pragma unroll
    for (int off = 1; off < 32; off <<= 1) {
        int y = __shfl_up_sync(0xffffffffu, x, off);
        if (lane >= off) x += y;
    }
    if (lane == 31) smbuf[warp] = x;
    __syncthreads();
    if (warp == 0) {
        int w = smbuf[lane];
        #pragma unroll
        for (int off = 1; off < 32; off <<= 1) {
            int y = __shfl_up_sync(0xffffffffu, w, off);
            if (lane >= off) w += y;
        }
        smbuf[lane] = w;
    }
    __syncthreads();
    int excl = ((warp > 0) ? smbuf[warp - 1] : 0) + x - local;
    for (int i = 0; i < per; i++) {
        start[base + i] = excl;
        cur[base + i]   = excl;
        excl += vals[i];
    }
    __syncthreads();
}

__global__ void scan_kernel()
{
    __shared__ int smbuf[32];
    block_scan_excl(g_cnt_e, g_start_e, g_cur_e, NE, smbuf);
    block_scan_excl(g_cnt_n, g_start_n, g_cur_n, N, smbuf);
}

__global__ void fill_kernel(const void* __restrict__ edge)
{
    int i = blockIdx.x * blockDim.x + threadIdx.x;
    if (i < NNZ) {
        int2 ne = load_edge(edge, i);
        if ((unsigned)ne.x < N && (unsigned)ne.y < NE) {
            int pe = atomicAdd(&g_cur_e[ne.y], 1);
            g_bucket_e[pe] = ne.x;
            int pn = atomicAdd(&g_cur_n[ne.x], 1);
            g_bucket_n[pn] = ne.y;
        }
    }
}

// e[he] = (1/deg) * sum over member nodes of xt[node]
__global__ void gather_e_kernel(const float* __restrict__ xt, float* __restrict__ e)
{
    int he = blockIdx.x;                 // NE blocks, 128 threads
    int tid = threadIdx.x;
    int s = g_start_e[he], dg = g_cnt_e[he];
    float acc = 0.0f;
    int j = 0;
    for (; j + 4 <= dg; j += 4) {
        int n0 = g_bucket_e[s + j], n1 = g_bucket_e[s + j + 1];
        int n2 = g_bucket_e[s + j + 2], n3 = g_bucket_e[s + j + 3];
        acc += xt[(size_t)n0 * D + tid] + xt[(size_t)n1 * D + tid]
             + xt[(size_t)n2 * D + tid] + xt[(size_t)n3 * D + tid];
    }
    for (; j < dg; j++)
        acc += xt[(size_t)g_bucket_e[s + j] * D + tid];
    float bi = (dg > 0) ? (1.0f / dg) : 0.0f;
    e[(size_t)he * D + tid] = acc * bi;
}

// out[node] = relu((1/deg) * sum over member hyperedges of e[he] + bh)
__global__ void gather_out_kernel(const float* __restrict__ e, const float* __restrict__ bh,
                                  float* __restrict__ out)
{
    int nd = blockIdx.x;                 // N blocks, 128 threads
    int tid = threadIdx.x;
    int s = g_start_n[nd], dg = g_cnt_n[nd];
    float acc = 0.0f;
    int j = 0;
    for (; j + 4 <= dg; j += 4) {
        int h0 = g_bucket_n[s + j], h1 = g_bucket_n[s + j + 1];
        int h2 = g_bucket_n[s + j + 2], h3 = g_bucket_n[s + j + 3];
        acc += e[(size_t)h0 * D + tid] + e[(size_t)h1 * D + tid]
             + e[(size_t)h2 * D + tid] + e[(size_t)h3 * D + tid];
    }
    for (; j < dg; j++)
        acc += e[(size_t)g_bucket_n[s + j] * D + tid];
    float di = (dg > 0) ? (1.0f / dg) : 0.0f;
    out[(size_t)nd * D + tid] = fmaxf(acc * di + bh[tid], 0.0f);
}

// ---------------- launch ----------------
extern "C" void kernel_launch(void* const* d_in, const int* in_sizes, int n_in,
                              void* d_out, int out_size)
{
    const float* x    = (const float*)d_in[0];
    const void*  edge = d_in[1];
    const float* Wq = (const float*)d_in[2],  *bq  = (const float*)d_in[3];
    const float* Wk = (const float*)d_in[4],  *bk  = (const float*)d_in[5];
    const float* Wv = (const float*)d_in[6],  *bv  = (const float*)d_in[7];
    const float* Wo = (const float*)d_in[8],  *bo  = (const float*)d_in[9];
    const float* g1 = (const float*)d_in[10], *b1  = (const float*)d_in[11];
    const float* W1 = (const float*)d_in[12], *bf1 = (const float*)d_in[13];
    const float* W2 = (const float*)d_in[14], *bf2 = (const float*)d_in[15];
    const float* g2 = (const float*)d_in[16], *b2  = (const float*)d_in[17];
    const float* Wh = (const float*)d_in[18], *bh  = (const float*)d_in[19];
    float* out = (float*)d_out;

    float *h, *q, *k, *v, *o, *z, *e;
    cudaGetSymbolAddress((void**)&h, g_h);
    cudaGetSymbolAddress((void**)&q, g_q);
    cudaGetSymbolAddress((void**)&k, g_k);
    cudaGetSymbolAddress((void**)&v, g_v);
    cudaGetSymbolAddress((void**)&o, g_o);
    cudaGetSymbolAddress((void**)&z, g_z);
    cudaGetSymbolAddress((void**)&e, g_e);

    const int FSMEM = (6 * 64 * TSTR + 128) * (int)sizeof(float);  // ~105 KB
    cudaFuncSetAttribute(flash_attn_tc, cudaFuncAttributeMaxDynamicSharedMemorySize, FSMEM);

    detect_edge_kernel<<<1, 32>>>((const int*)edge);

    // CSR build (independent of transformer; runs early in the stream)
    zero_counts_kernel<<<(N + 255) / 256, 256>>>();
    count_kernel<<<NNZ / 256, 256>>>(edge);
    scan_kernel<<<1, 1024>>>();
    fill_kernel<<<NNZ / 256, 256>>>(edge);

    dim3 gD(D / 64, N / 64);       // 2 x 64
    dim3 gF(FF / 64, N / 64);      // 4 x 64
    dim3 gQKV(D / 64, N / 64, 3);  // 2 x 64 x 3

    for (int it = 0; it < 2; ++it) {
        const float* hin = (it == 0) ? x : h;
        qkv_gemm_tc<<<gQKV, 256>>>(hin, Wq, bq, Wk, bk, Wv, bv, q, k, v);
        flash_attn_tc<<<dim3(N / 64, H), 256, FSMEM>>>(q, k, v, o);
        gemm_ln_tc<<<N / 32, 256>>>(o, Wo, bo, hin, g1, b1, h, D);
        gemm_tc<<<gF, 256>>>(h, W1, bf1, z, FF, D, 1);
        gemm_ln_tc<<<N / 32, 256>>>(z, W2, bf2, h, g2, b2, h, FF);
    }

    // xt = h @ Wh (reuse q buffer)
    gemm_tc<<<gD, 256>>>(h, Wh, nullptr, q, D, D, 0);

    gather_e_kernel<<<NE, 128>>>(q, e);
    gather_out_kernel<<<N, 128>>>(e, bh, out);
}

// round 14
// speedup vs baseline: 3.1407x; 1.1622x over previous
#include <cuda_runtime.h>
#include <cuda_bf16.h>
#include <math.h>

#define N   4096
#define D   128
#define H   2
#define DH  64
#define FF  256
#define NE  2048
#define NNZ 65536
#define EPS 1e-5f

typedef unsigned long long u64;
typedef unsigned int u32;

// ---------------- tf32 helpers ----------------
__device__ __forceinline__ u32 f2tf32(float x) {
    u32 r; asm("cvt.rna.tf32.f32 %0, %1;" : "=r"(r) : "f"(x)); return r;
}
__device__ __forceinline__ void mma_tf32(float& d0, float& d1, float& d2, float& d3,
                                         u32 a0, u32 a1, u32 a2, u32 a3,
                                         u32 b0, u32 b1)
{
    asm("mma.sync.aligned.m16n8k8.row.col.f32.tf32.tf32.f32 "
        "{%0,%1,%2,%3},{%4,%5,%6,%7},{%8,%9},{%0,%1,%2,%3};"
        : "+f"(d0), "+f"(d1), "+f"(d2), "+f"(d3)
        : "r"(a0), "r"(a1), "r"(a2), "r"(a3), "r"(b0), "r"(b1));
}

// ---------------- scratch (no allocation allowed) ----------------
__device__ float g_h[N * D];
__device__ float g_q[N * D];
__device__ float g_k[N * D];
__device__ float g_v[N * D];
__device__ float g_o[N * D];
__device__ float g_z[N * FF];
__device__ float g_e[NE * D];
__device__ int   g_edge_is64;
// CSR scratch
__device__ int g_cnt_e[NE], g_cnt_n[N];
__device__ int g_start_e[NE], g_start_n[N];
__device__ int g_cur_e[NE], g_cur_n[N];
__device__ int g_bucket_e[NNZ];   // node indices grouped by hyperedge
__device__ int g_bucket_n[NNZ];   // hyperedge indices grouped by node

// ---------------- edge dtype detection ----------------
__global__ void detect_edge_kernel(const int* __restrict__ e32)
{
    if (threadIdx.x == 0 && blockIdx.x == 0) {
        int is64 = 1;
        #pragma unroll
        for (int i = 1; i < 64; i += 2)
            if (e32[i] != 0) is64 = 0;
        g_edge_is64 = is64;
    }
}

__device__ __forceinline__ int2 load_edge(const void* __restrict__ edge, int nz)
{
    if (g_edge_is64) {
        const long long* e = (const long long*)edge;
        return make_int2((int)e[nz], (int)e[NNZ + nz]);
    } else {
        const int* e = (const int*)edge;
        return make_int2(e[nz], e[NNZ + nz]);
    }
}

// ======= tf32 tensor-core GEMM: C = act(A @ B + bias), 64x64 tile, KC=32 =======
#define GSTR 36
struct GemmTcSmem { u32 As[64 * GSTR]; u32 Bs[64 * GSTR]; };

__device__ __forceinline__ void gemm_tile_tc(const float* __restrict__ A,
                                             const float* __restrict__ B,
                                             const float* __restrict__ bias,
                                             float* __restrict__ C,
                                             int Nc, int K, int act,
                                             int row0, int col0, GemmTcSmem& sm)
{
    int tid = threadIdx.x;
    int wid = tid >> 5, lane = tid & 31;
    int g = lane >> 2, tig = lane & 3;
    int wm = wid & 3, wn = wid >> 2;
    int r0 = wm * 16, n0 = wn * 32;

    float areg[8], breg[8];
    #pragma unroll
    for (int i = 0; i < 8; i++) {
        int idx = tid + i * 256;
        int am = idx >> 5, ak = idx & 31;
        areg[i] = A[(size_t)(row0 + am) * K + ak];
        int bk = idx >> 6, bn = idx & 63;
        breg[i] = B[(size_t)bk * Nc + col0 + bn];
    }

    float acc[4][4] = {};
    for (int k0 = 0; k0 < K; k0 += 32) {
        __syncthreads();
        #pragma unroll
        for (int i = 0; i < 8; i++) {
            int idx = tid + i * 256;
            int am = idx >> 5, ak = idx & 31;
            sm.As[am * GSTR + ak] = f2tf32(areg[i]);
            int bk = idx >> 6, bn = idx & 63;
            sm.Bs[bn * GSTR + bk] = f2tf32(breg[i]);
        }
        __syncthreads();
        if (k0 + 32 < K) {
            #pragma unroll
            for (int i = 0; i < 8; i++) {
                int idx = tid + i * 256;
                int am = idx >> 5, ak = idx & 31;
                areg[i] = A[(size_t)(row0 + am) * K + (k0 + 32) + ak];
                int bk = idx >> 6, bn = idx & 63;
                breg[i] = B[(size_t)(k0 + 32 + bk) * Nc + col0 + bn];
            }
        }
        #pragma unroll
        for (int ks = 0; ks < 4; ks++) {
            int kk = ks * 8;
            u32 a0 = sm.As[(r0 + g) * GSTR + kk + tig];
            u32 a1 = sm.As[(r0 + g + 8) * GSTR + kk + tig];
            u32 a2 = sm.As[(r0 + g) * GSTR + kk + tig + 4];
            u32 a3 = sm.As[(r0 + g + 8) * GSTR + kk + tig + 4];
            #pragma unroll
            for (int nt = 0; nt < 4; nt++) {
                int n = n0 + nt * 8;
                u32 b0 = sm.Bs[(n + g) * GSTR + kk + tig];
                u32 b1 = sm.Bs[(n + g) * GSTR + kk + tig + 4];
                mma_tf32(acc[nt][0], acc[nt][1], acc[nt][2], acc[nt][3],
                         a0, a1, a2, a3, b0, b1);
            }
        }
    }

    int ra = row0 + r0 + g, rb = ra + 8;
    #pragma unroll
    for (int nt = 0; nt < 4; nt++) {
        int c = col0 + n0 + nt * 8 + 2 * tig;
        float bc0 = bias ? bias[c] : 0.0f;
        float bc1 = bias ? bias[c + 1] : 0.0f;
        float v0 = acc[nt][0] + bc0, v1 = acc[nt][1] + bc1;
        float v2 = acc[nt][2] + bc0, v3 = acc[nt][3] + bc1;
        if (act == 1) {
            v0 = 1.0f / (1.0f + __expf(-v0));
            v1 = 1.0f / (1.0f + __expf(-v1));
            v2 = 1.0f / (1.0f + __expf(-v2));
            v3 = 1.0f / (1.0f + __expf(-v3));
        }
        *(float2*)&C[(size_t)ra * Nc + c] = make_float2(v0, v1);
        *(float2*)&C[(size_t)rb * Nc + c] = make_float2(v2, v3);
    }
}

__global__ void gemm_tc(const float* __restrict__ A, const float* __restrict__ B,
                        const float* __restrict__ bias, float* __restrict__ C,
                        int Nc, int K, int act)
{
    __shared__ GemmTcSmem sm;
    gemm_tile_tc(A, B, bias, C, Nc, K, act, blockIdx.y * 64, blockIdx.x * 64, sm);
}

__global__ void qkv_gemm_tc(const float* __restrict__ A,
                            const float* __restrict__ Wq, const float* __restrict__ bq,
                            const float* __restrict__ Wk, const float* __restrict__ bk,
                            const float* __restrict__ Wv, const float* __restrict__ bv,
                            float* __restrict__ q, float* __restrict__ k, float* __restrict__ v)
{
    __shared__ GemmTcSmem sm;
    const float* B; const float* bias; float* C;
    if (blockIdx.z == 0)      { B = Wq; bias = bq; C = q; }
    else if (blockIdx.z == 1) { B = Wk; bias = bk; C = k; }
    else                      { B = Wv; bias = bv; C = v; }
    gemm_tile_tc(A, B, bias, C, D, D, 0, blockIdx.y * 64, blockIdx.x * 64, sm);
}

// ======= fused GEMM + residual + LayerNorm: C = LN(hin + A@B + bias) =======
// Tile 32 rows x 128 cols (full D) -> grid = N/32 = 128 CTAs.
struct GemmLnSmem {
    u32 As[32 * GSTR];
    u32 Bs[128 * GSTR];
    float ps[32 * 4];
    float pq[32 * 4];
};

__global__ void gemm_ln_tc(const float* __restrict__ A, const float* __restrict__ B,
                           const float* __restrict__ bias, const float* __restrict__ hin,
                           const float* __restrict__ lng, const float* __restrict__ lnb,
                           float* __restrict__ C, int K)
{
    __shared__ GemmLnSmem sm;
    int tid = threadIdx.x;
    int wid = tid >> 5, lane = tid & 31;
    int gq = lane >> 2, tig = lane & 3;
    int wm = wid & 1, wn = wid >> 1;     // 2 x 4
    int r0 = wm * 16, n0 = wn * 32;
    int row0 = blockIdx.x * 32;

    float areg[4], breg[16];
    #pragma unroll
    for (int i = 0; i < 4; i++) {
        int idx = tid + i * 256;
        int am = idx >> 5, ak = idx & 31;
        areg[i] = A[(size_t)(row0 + am) * K + ak];
    }
    #pragma unroll
    for (int i = 0; i < 16; i++) {
        int idx = tid + i * 256;
        int bk = idx >> 7, bn = idx & 127;
        breg[i] = B[(size_t)bk * D + bn];
    }

    float acc[4][4] = {};
    for (int k0 = 0; k0 < K; k0 += 32) {
        __syncthreads();
        #pragma unroll
        for (int i = 0; i < 4; i++) {
            int idx = tid + i * 256;
            int am = idx >> 5, ak = idx & 31;
            sm.As[am * GSTR + ak] = f2tf32(areg[i]);
        }
        #pragma unroll
        for (int i = 0; i < 16; i++) {
            int idx = tid + i * 256;
            int bk = idx >> 7, bn = idx & 127;
            sm.Bs[bn * GSTR + bk] = f2tf32(breg[i]);
        }
        __syncthreads();
        if (k0 + 32 < K) {
            #pragma unroll
            for (int i = 0; i < 4; i++) {
                int idx = tid + i * 256;
                int am = idx >> 5, ak = idx & 31;
                areg[i] = A[(size_t)(row0 + am) * K + (k0 + 32) + ak];
            }
            #pragma unroll
            for (int i = 0; i < 16; i++) {
                int idx = tid + i * 256;
                int bk = idx >> 7, bn = idx & 127;
                breg[i] = B[(size_t)(k0 + 32 + bk) * D + bn];
            }
        }
        #pragma unroll
        for (int ks = 0; ks < 4; ks++) {
            int kk = ks * 8;
            u32 a0 = sm.As[(r0 + gq) * GSTR + kk + tig];
            u32 a1 = sm.As[(r0 + gq + 8) * GSTR + kk + tig];
            u32 a2 = sm.As[(r0 + gq) * GSTR + kk + tig + 4];
            u32 a3 = sm.As[(r0 + gq + 8) * GSTR + kk + tig + 4];
            #pragma unroll
            for (int nt = 0; nt < 4; nt++) {
                int n = n0 + nt * 8;
                u32 b0 = sm.Bs[(n + gq) * GSTR + kk + tig];
                u32 b1 = sm.Bs[(n + gq) * GSTR + kk + tig + 4];
                mma_tf32(acc[nt][0], acc[nt][1], acc[nt][2], acc[nt][3],
                         a0, a1, a2, a3, b0, b1);
            }
        }
    }

    int ra = row0 + r0 + gq, rb = ra + 8;
    float va[4][2], vb[4][2];
    float sa = 0.0f, qa = 0.0f, sb = 0.0f, qb = 0.0f;
    #pragma unroll
    for (int nt = 0; nt < 4; nt++) {
        int c = n0 + nt * 8 + 2 * tig;
        float2 bc  = *(const float2*)&bias[c];
        float2 ha  = *(const float2*)&hin[(size_t)ra * D + c];
        float2 hb  = *(const float2*)&hin[(size_t)rb * D + c];
        va[nt][0] = acc[nt][0] + bc.x + ha.x;
        va[nt][1] = acc[nt][1] + bc.y + ha.y;
        vb[nt][0] = acc[nt][2] + bc.x + hb.x;
        vb[nt][1] = acc[nt][3] + bc.y + hb.y;
        sa += va[nt][0] + va[nt][1];
        qa += va[nt][0] * va[nt][0] + va[nt][1] * va[nt][1];
        sb += vb[nt][0] + vb[nt][1];
        qb += vb[nt][0] * vb[nt][0] + vb[nt][1] * vb[nt][1];
    }
    #pragma unroll
    for (int off = 1; off <= 2; off <<= 1) {
        sa += __shfl_xor_sync(0xffffffffu, sa, off);
        qa += __shfl_xor_sync(0xffffffffu, qa, off);
        sb += __shfl_xor_sync(0xffffffffu, sb, off);
        qb += __shfl_xor_sync(0xffffffffu, qb, off);
    }
    if (tig == 0) {
        sm.ps[(r0 + gq) * 4 + wn] = sa;     sm.pq[(r0 + gq) * 4 + wn] = qa;
        sm.ps[(r0 + gq + 8) * 4 + wn] = sb; sm.pq[(r0 + gq + 8) * 4 + wn] = qb;
    }
    __syncthreads();
    int ia4 = (r0 + gq) * 4, ib4 = (r0 + gq + 8) * 4;
    float Sa = sm.ps[ia4] + sm.ps[ia4 + 1] + sm.ps[ia4 + 2] + sm.ps[ia4 + 3];
    float Qa = sm.pq[ia4] + sm.pq[ia4 + 1] + sm.pq[ia4 + 2] + sm.pq[ia4 + 3];
    float Sb = sm.ps[ib4] + sm.ps[ib4 + 1] + sm.ps[ib4 + 2] + sm.ps[ib4 + 3];
    float Qb = sm.pq[ib4] + sm.pq[ib4 + 1] + sm.pq[ib4 + 2] + sm.pq[ib4 + 3];
    float ma = Sa * (1.0f / D), vva = Qa * (1.0f / D) - ma * ma;
    float mb = Sb * (1.0f / D), vvb = Qb * (1.0f / D) - mb * mb;
    float ia = rsqrtf(vva + EPS), ib = rsqrtf(vvb + EPS);
    #pragma unroll
    for (int nt = 0; nt < 4; nt++) {
        int c = n0 + nt * 8 + 2 * tig;
        float2 gg = *(const float2*)&lng[c];
        float2 bb = *(const float2*)&lnb[c];
        *(float2*)&C[(size_t)ra * D + c] =
            make_float2((va[nt][0] - ma) * ia * gg.x + bb.x,
                        (va[nt][1] - ma) * ia * gg.y + bb.y);
        *(float2*)&C[(size_t)rb * D + c] =
            make_float2((vb[nt][0] - mb) * ib * gg.x + bb.x,
                        (vb[nt][1] - mb) * ib * gg.y + bb.y);
    }
}

// ======= flash attention, tf32 MMA, no-max softmax (bounded scores), 2 barriers/iter =======
#define TSTR 68
__global__ void flash_attn_tc(const float* __restrict__ q, const float* __restrict__ k,
                              const float* __restrict__ v, float* __restrict__ o)
{
    extern __shared__ float fsm[];
    // regions of 64*TSTR floats: 0=Qs, 1=Ks0, 2=Ks1, 3=Vs0, 4=Vs1, 5=Ps(tf32 bits)
    float* Qs = fsm;
    u32*   PsU = (u32*)(fsm + 5 * 64 * TSTR);
    float* l_part = fsm + 6 * 64 * TSTR;   // [64][2]
    u32* QsU = (u32*)Qs;

    int tid  = threadIdx.x;
    int wid  = tid >> 5, lane = tid & 31;
    int g    = lane >> 2, tig = lane & 3;
    int wm   = wid & 3, wn = wid >> 2;
    int r0   = wm * 16, n0 = wn * 32;
    int qrow0 = blockIdx.x * 64;
    int hcol  = blockIdx.y * DH;

    #pragma unroll
    for (int i = 0; i < 16; i++) {
        int idx = tid + i * 256;
        int r = idx >> 6, d = idx & 63;
        QsU[r * TSTR + d] = f2tf32(q[(size_t)(qrow0 + r) * D + hcol + d]);
    }

    float kreg[16], vreg[16];
    #pragma unroll
    for (int i = 0; i < 16; i++) {
        int idx = tid + i * 256;
        int c = idx >> 6, d = idx & 63;
        kreg[i] = k[(size_t)c * D + hcol + d];
        vreg[i] = v[(size_t)c * D + hcol + d];
    }
    __syncthreads();

    // hoist Q fragments (loop-invariant)
    u32 qa[8][4];
    #pragma unroll
    for (int ks = 0; ks < 8; ks++) {
        int k0 = ks * 8;
        qa[ks][0] = QsU[(r0 + g) * TSTR + k0 + tig];
        qa[ks][1] = QsU[(r0 + g + 8) * TSTR + k0 + tig];
        qa[ks][2] = QsU[(r0 + g) * TSTR + k0 + tig + 4];
        qa[ks][3] = QsU[(r0 + g + 8) * TSTR + k0 + tig + 4];
    }

    const float scale = 0.125f;
    float la = 0.0f, lb = 0.0f;   // unnormalized row sums (this thread's cols)
    float of[4][4] = {};
    int p = 0;

    for (int kb = 0; kb < N; kb += 64) {
        u32* KsU = (u32*)(fsm + (1 + p) * 64 * TSTR);
        u32* VsU = (u32*)(fsm + (3 + p) * 64 * TSTR);
        #pragma unroll
        for (int i = 0; i < 16; i++) {
            int idx = tid + i * 256;
            int c = idx >> 6, d = idx & 63;
            KsU[c * TSTR + d] = f2tf32(kreg[i]);
            VsU[d * TSTR + c] = f2tf32(vreg[i]);
        }
        __syncthreads();                       // barrier A
        if (kb + 64 < N) {
            #pragma unroll
            for (int i = 0; i < 16; i++) {
                int idx = tid + i * 256;
                int c = idx >> 6, d = idx & 63;
                kreg[i] = k[(size_t)(kb + 64 + c) * D + hcol + d];
                vreg[i] = v[(size_t)(kb + 64 + c) * D + hcol + d];
            }
        }

        // S = Q @ K^T, then exp in-register, store P(tf32), accumulate l
        {
            float sf[4][4] = {};
            #pragma unroll
            for (int ks = 0; ks < 8; ks++) {
                int k0 = ks * 8;
                #pragma unroll
                for (int nt = 0; nt < 4; nt++) {
                    int n = n0 + nt * 8;
                    u32 b0 = KsU[(n + g) * TSTR + k0 + tig];
                    u32 b1 = KsU[(n + g) * TSTR + k0 + tig + 4];
                    mma_tf32(sf[nt][0], sf[nt][1], sf[nt][2], sf[nt][3],
                             qa[ks][0], qa[ks][1], qa[ks][2], qa[ks][3], b0, b1);
                }
            }
            #pragma unroll
            for (int nt = 0; nt < 4; nt++) {
                float p0 = __expf(sf[nt][0] * scale);
                float p1 = __expf(sf[nt][1] * scale);
                float p2 = __expf(sf[nt][2] * scale);
                float p3 = __expf(sf[nt][3] * scale);
                la += p0 + p1;
                lb += p2 + p3;
                int n = n0 + nt * 8 + 2 * tig;
                *(uint2*)&PsU[(r0 + g) * TSTR + n]     = make_uint2(f2tf32(p0), f2tf32(p1));
                *(uint2*)&PsU[(r0 + g + 8) * TSTR + n] = make_uint2(f2tf32(p2), f2tf32(p3));
            }
        }
        __syncthreads();                       // barrier B

        // O += P @ V
        #pragma unroll
        for (int ks = 0; ks < 8; ks++) {
            int k0 = ks * 8;
            u32 a0 = PsU[(r0 + g) * TSTR + k0 + tig];
            u32 a1 = PsU[(r0 + g + 8) * TSTR + k0 + tig];
            u32 a2 = PsU[(r0 + g) * TSTR + k0 + tig + 4];
            u32 a3 = PsU[(r0 + g + 8) * TSTR + k0 + tig + 4];
            #pragma unroll
            for (int nt = 0; nt < 4; nt++) {
                int n = n0 + nt * 8;
                u32 b0 = VsU[(n + g) * TSTR + k0 + tig];
                u32 b1 = VsU[(n + g) * TSTR + k0 + tig + 4];
                mma_tf32(of[nt][0], of[nt][1], of[nt][2], of[nt][3],
                         a0, a1, a2, a3, b0, b1);
            }
        }
        p ^= 1;
    }

    // reduce l over tig (quad), then across the 2 n-warps via smem
    la += __shfl_xor_sync(0xffffffffu, la, 1);
    la += __shfl_xor_sync(0xffffffffu, la, 2);
    lb += __shfl_xor_sync(0xffffffffu, lb, 1);
    lb += __shfl_xor_sync(0xffffffffu, lb, 2);
    __syncthreads();
    if (tig == 0) {
        l_part[(r0 + g) * 2 + wn]     = la;
        l_part[(r0 + g + 8) * 2 + wn] = lb;
    }
    __syncthreads();
    float linv  = 1.0f / (l_part[(r0 + g) * 2]     + l_part[(r0 + g) * 2 + 1]);
    float linv8 = 1.0f / (l_part[(r0 + g + 8) * 2] + l_part[(r0 + g + 8) * 2 + 1]);
    #pragma unroll
    for (int nt = 0; nt < 4; nt++) {
        int n = hcol + n0 + nt * 8 + 2 * tig;
        int ra = qrow0 + r0 + g, rb = qrow0 + r0 + g + 8;
        *(float2*)&o[(size_t)ra * D + n] = make_float2(of[nt][0] * linv,  of[nt][1] * linv);
        *(float2*)&o[(size_t)rb * D + n] = make_float2(of[nt][2] * linv8, of[nt][3] * linv8);
    }
}

// ======= hypergraph conv via CSR build + gather (no float atomics) =======
__global__ void zero_counts_kernel()
{
    int i = blockIdx.x * blockDim.x + threadIdx.x;
    if (i < NE) g_cnt_e[i] = 0;
    if (i < N)  g_cnt_n[i] = 0;
}

__global__ void count_kernel(const void* __restrict__ edge)
{
    int i = blockIdx.x * blockDim.x + threadIdx.x;
    if (i < NNZ) {
        int2 ne = load_edge(edge, i);
        if ((unsigned)ne.x < N && (unsigned)ne.y < NE) {
            atomicAdd(&g_cnt_n[ne.x], 1);
            atomicAdd(&g_cnt_e[ne.y], 1);
        }
    }
}

__device__ void block_scan_excl(const int* cnt, int* start, int* cur, int n, int* smbuf)
{
    int tid = threadIdx.x;               // 1024 threads
    int per = n >> 10;
    int base = tid * per;
    int vals[4];
    int local = 0;
    for (int i = 0; i < per; i++) { vals[i] = cnt[base + i]; local += vals[i]; }
    int lane = tid & 31, warp = tid >> 5;
    int x = local;
    #pragma unroll
    for (int off = 1; off < 32; off <<= 1) {
        int y = __shfl_up_sync(0xffffffffu, x, off);
        if (lane >= off) x += y;
    }
    if (lane == 31) smbuf[warp] = x;
    __syncthreads();
    if (warp == 0) {
        int w = smbuf[lane];
        #pragma unroll
        for (int off = 1; off < 32; off <<= 1) {
            int y = __shfl_up_sync(0xffffffffu, w, off);
            if (lane >= off) w += y;
        }
        smbuf[lane] = w;
    }
    __syncthreads();
    int excl = ((warp > 0) ? smbuf[warp - 1] : 0) + x - local;
    for (int i = 0; i < per; i++) {
        start[base + i] = excl;
        cur[base + i]   = excl;
        excl += vals[i];
    }
    __syncthreads();
}

__global__ void scan_kernel()
{
    __shared__ int smbuf[32];
    if (blockIdx.x == 0)
        block_scan_excl(g_cnt_e, g_start_e, g_cur_e, NE, smbuf);
    else
        block_scan_excl(g_cnt_n, g_start_n, g_cur_n, N, smbuf);
}

__global__ void fill_kernel(const void* __restrict__ edge)
{
    int i = blockIdx.x * blockDim.x + threadIdx.x;
    if (i < NNZ) {
        int2 ne = load_edge(edge, i);
        if ((unsigned)ne.x < N && (unsigned)ne.y < NE) {
            int pe = atomicAdd(&g_cur_e[ne.y], 1);
            g_bucket_e[pe] = ne.x;
            int pn = atomicAdd(&g_cur_n[ne.x], 1);
            g_bucket_n[pn] = ne.y;
        }
    }
}

__global__ void gather_e_kernel(const float* __restrict__ xt, float* __restrict__ e)
{
    int he = blockIdx.x;                 // NE blocks, 128 threads
    int tid = threadIdx.x;
    int s = g_start_e[he], dg = g_cnt_e[he];
    float acc = 0.0f;
    int j = 0;
    for (; j + 4 <= dg; j += 4) {
        int n0 = g_bucket_e[s + j], n1 = g_bucket_e[s + j + 1];
        int n2 = g_bucket_e[s + j + 2], n3 = g_bucket_e[s + j + 3];
        acc += xt[(size_t)n0 * D + tid] + xt[(size_t)n1 * D + tid]
             + xt[(size_t)n2 * D + tid] + xt[(size_t)n3 * D + tid];
    }
    for (; j < dg; j++)
        acc += xt[(size_t)g_bucket_e[s + j] * D + tid];
    float bi = (dg > 0) ? (1.0f / dg) : 0.0f;
    e[(size_t)he * D + tid] = acc * bi;
}

__global__ void gather_out_kernel(const float* __restrict__ e, const float* __restrict__ bh,
                                  float* __restrict__ out)
{
    int nd = blockIdx.x;                 // N blocks, 128 threads
    int tid = threadIdx.x;
    int s = g_start_n[nd], dg = g_cnt_n[nd];
    float acc = 0.0f;
    int j = 0;
    for (; j + 4 <= dg; j += 4) {
        int h0 = g_bucket_n[s + j], h1 = g_bucket_n[s + j + 1];
        int h2 = g_bucket_n[s + j + 2], h3 = g_bucket_n[s + j + 3];
        acc += e[(size_t)h0 * D + tid] + e[(size_t)h1 * D + tid]
             + e[(size_t)h2 * D + tid] + e[(size_t)h3 * D + tid];
    }
    for (; j < dg; j++)
        acc += e[(size_t)g_bucket_n[s + j] * D + tid];
    float di = (dg > 0) ? (1.0f / dg) : 0.0f;
    out[(size_t)nd * D + tid] = fmaxf(acc * di + bh[tid], 0.0f);
}

// ---------------- launch ----------------
extern "C" void kernel_launch(void* const* d_in, const int* in_sizes, int n_in,
                              void* d_out, int out_size)
{
    const float* x    = (const float*)d_in[0];
    const void*  edge = d_in[1];
    const float* Wq = (const float*)d_in[2],  *bq  = (const float*)d_in[3];
    const float* Wk = (const float*)d_in[4],  *bk  = (const float*)d_in[5];
    const float* Wv = (const float*)d_in[6],  *bv  = (const float*)d_in[7];
    const float* Wo = (const float*)d_in[8],  *bo  = (const float*)d_in[9];
    const float* g1 = (const float*)d_in[10], *b1  = (const float*)d_in[11];
    const float* W1 = (const float*)d_in[12], *bf1 = (const float*)d_in[13];
    const float* W2 = (const float*)d_in[14], *bf2 = (const float*)d_in[15];
    const float* g2 = (const float*)d_in[16], *b2  = (const float*)d_in[17];
    const float* Wh = (const float*)d_in[18], *bh  = (const float*)d_in[19];
    float* out = (float*)d_out;

    float *h, *q, *k, *v, *o, *z, *e;
    cudaGetSymbolAddress((void**)&h, g_h);
    cudaGetSymbolAddress((void**)&q, g_q);
    cudaGetSymbolAddress((void**)&k, g_k);
    cudaGetSymbolAddress((void**)&v, g_v);
    cudaGetSymbolAddress((void**)&o, g_o);
    cudaGetSymbolAddress((void**)&z, g_z);
    cudaGetSymbolAddress((void**)&e, g_e);

    const int FSMEM = (6 * 64 * TSTR + 128) * (int)sizeof(float);  // ~105 KB
    cudaFuncSetAttribute(flash_attn_tc, cudaFuncAttributeMaxDynamicSharedMemorySize, FSMEM);

    detect_edge_kernel<<<1, 32>>>((const int*)edge);

    // CSR build (independent of transformer; runs early in the stream)
    zero_counts_kernel<<<(N + 255) / 256, 256>>>();
    count_kernel<<<NNZ / 256, 256>>>(edge);
    scan_kernel<<<2, 1024>>>();
    fill_kernel<<<NNZ / 256, 256>>>(edge);

    dim3 gD(D / 64, N / 64);       // 2 x 64
    dim3 gF(FF / 64, N / 64);      // 4 x 64
    dim3 gQKV(D / 64, N / 64, 3);  // 2 x 64 x 3

    for (int it = 0; it < 2; ++it) {
        const float* hin = (it == 0) ? x : h;
        qkv_gemm_tc<<<gQKV, 256>>>(hin, Wq, bq, Wk, bk, Wv, bv, q, k, v);
        flash_attn_tc<<<dim3(N / 64, H), 256, FSMEM>>>(q, k, v, o);
        gemm_ln_tc<<<N / 32, 256>>>(o, Wo, bo, hin, g1, b1, h, D);
        gemm_tc<<<gF, 256>>>(h, W1, bf1, z, FF, D, 1);
        gemm_ln_tc<<<N / 32, 256>>>(z, W2, bf2, h, g2, b2, h, FF);
    }

    // xt = h @ Wh (reuse q buffer)
    gemm_tc<<<gD, 256>>>(h, Wh, nullptr, q, D, D, 0);

    gather_e_kernel<<<NE, 128>>>(q, e);
    gather_out_kernel<<<N, 128>>>(e, bh, out);
}

// round 16
// speedup vs baseline: 3.2209x; 1.0255x over previous
#include <cuda_runtime.h>
#include <cuda_bf16.h>
#include <math.h>

#define N   4096
#define D   128
#define H   2
#define DH  64
#define FF  256
#define NE  2048
#define NNZ 65536
#define EPS 1e-5f

typedef unsigned long long u64;
typedef unsigned int u32;

// ---------------- tf32 helpers ----------------
__device__ __forceinline__ u32 f2tf32(float x) {
    u32 r; asm("cvt.rna.tf32.f32 %0, %1;" : "=r"(r) : "f"(x)); return r;
}
__device__ __forceinline__ void mma_tf32(float& d0, float& d1, float& d2, float& d3,
                                         u32 a0, u32 a1, u32 a2, u32 a3,
                                         u32 b0, u32 b1)
{
    asm("mma.sync.aligned.m16n8k8.row.col.f32.tf32.tf32.f32 "
        "{%0,%1,%2,%3},{%4,%5,%6,%7},{%8,%9},{%0,%1,%2,%3};"
        : "+f"(d0), "+f"(d1), "+f"(d2), "+f"(d3)
        : "r"(a0), "r"(a1), "r"(a2), "r"(a3), "r"(b0), "r"(b1));
}

// ---------------- scratch (no allocation allowed) ----------------
__device__ float g_h[N * D];
__device__ float g_q[N * D];
__device__ float g_k[N * D];
__device__ float g_v[N * D];
__device__ float g_o[N * D];
__device__ float g_z[N * FF];
__device__ float g_e[NE * D];
__device__ int   g_edge_is64;
// CSR scratch
__device__ int g_cnt_e[NE], g_cnt_n[N];
__device__ int g_start_e[NE], g_start_n[N];
__device__ int g_cur_e[NE], g_cur_n[N];
__device__ int g_bucket_e[NNZ];   // node indices grouped by hyperedge
__device__ int g_bucket_n[NNZ];   // hyperedge indices grouped by node

// ---------------- edge dtype detection ----------------
__global__ void detect_edge_kernel(const int* __restrict__ e32)
{
    if (threadIdx.x == 0 && blockIdx.x == 0) {
        int is64 = 1;
        #pragma unroll
        for (int i = 1; i < 64; i += 2)
            if (e32[i] != 0) is64 = 0;
        g_edge_is64 = is64;
    }
}

__device__ __forceinline__ int2 load_edge(const void* __restrict__ edge, int nz)
{
    if (g_edge_is64) {
        const long long* e = (const long long*)edge;
        return make_int2((int)e[nz], (int)e[NNZ + nz]);
    } else {
        const int* e = (const int*)edge;
        return make_int2(e[nz], e[NNZ + nz]);
    }
}

// ======= tf32 tensor-core GEMM: C = act(A @ B + bias), 64x64 tile, KC=32 =======
#define GSTR 36
struct GemmTcSmem { u32 As[64 * GSTR]; u32 Bs[64 * GSTR]; };

__device__ __forceinline__ void gemm_tile_tc(const float* __restrict__ A,
                                             const float* __restrict__ B,
                                             const float* __restrict__ bias,
                                             float* __restrict__ C,
                                             int Nc, int K, int act,
                                             int row0, int col0, GemmTcSmem& sm)
{
    int tid = threadIdx.x;
    int wid = tid >> 5, lane = tid & 31;
    int g = lane >> 2, tig = lane & 3;
    int wm = wid & 3, wn = wid >> 2;
    int r0 = wm * 16, n0 = wn * 32;

    float areg[8], breg[8];
    #pragma unroll
    for (int i = 0; i < 8; i++) {
        int idx = tid + i * 256;
        int am = idx >> 5, ak = idx & 31;
        areg[i] = A[(size_t)(row0 + am) * K + ak];
        int bk = idx >> 6, bn = idx & 63;
        breg[i] = B[(size_t)bk * Nc + col0 + bn];
    }

    float acc[4][4] = {};
    for (int k0 = 0; k0 < K; k0 += 32) {
        __syncthreads();
        #pragma unroll
        for (int i = 0; i < 8; i++) {
            int idx = tid + i * 256;
            int am = idx >> 5, ak = idx & 31;
            sm.As[am * GSTR + ak] = f2tf32(areg[i]);
            int bk = idx >> 6, bn = idx & 63;
            sm.Bs[bn * GSTR + bk] = f2tf32(breg[i]);
        }
        __syncthreads();
        if (k0 + 32 < K) {
            #pragma unroll
            for (int i = 0; i < 8; i++) {
                int idx = tid + i * 256;
                int am = idx >> 5, ak = idx & 31;
                areg[i] = A[(size_t)(row0 + am) * K + (k0 + 32) + ak];
                int bk = idx >> 6, bn = idx & 63;
                breg[i] = B[(size_t)(k0 + 32 + bk) * Nc + col0 + bn];
            }
        }
        #pragma unroll
        for (int ks = 0; ks < 4; ks++) {
            int kk = ks * 8;
            u32 a0 = sm.As[(r0 + g) * GSTR + kk + tig];
            u32 a1 = sm.As[(r0 + g + 8) * GSTR + kk + tig];
            u32 a2 = sm.As[(r0 + g) * GSTR + kk + tig + 4];
            u32 a3 = sm.As[(r0 + g + 8) * GSTR + kk + tig + 4];
            #pragma unroll
            for (int nt = 0; nt < 4; nt++) {
                int n = n0 + nt * 8;
                u32 b0 = sm.Bs[(n + g) * GSTR + kk + tig];
                u32 b1 = sm.Bs[(n + g) * GSTR + kk + tig + 4];
                mma_tf32(acc[nt][0], acc[nt][1], acc[nt][2], acc[nt][3],
                         a0, a1, a2, a3, b0, b1);
            }
        }
    }

    int ra = row0 + r0 + g, rb = ra + 8;
    #pragma unroll
    for (int nt = 0; nt < 4; nt++) {
        int c = col0 + n0 + nt * 8 + 2 * tig;
        float bc0 = bias ? bias[c] : 0.0f;
        float bc1 = bias ? bias[c + 1] : 0.0f;
        float v0 = acc[nt][0] + bc0, v1 = acc[nt][1] + bc1;
        float v2 = acc[nt][2] + bc0, v3 = acc[nt][3] + bc1;
        if (act == 1) {
            v0 = 1.0f / (1.0f + __expf(-v0));
            v1 = 1.0f / (1.0f + __expf(-v1));
            v2 = 1.0f / (1.0f + __expf(-v2));
            v3 = 1.0f / (1.0f + __expf(-v3));
        }
        *(float2*)&C[(size_t)ra * Nc + c] = make_float2(v0, v1);
        *(float2*)&C[(size_t)rb * Nc + c] = make_float2(v2, v3);
    }
}

__global__ void gemm_tc(const float* __restrict__ A, const float* __restrict__ B,
                        const float* __restrict__ bias, float* __restrict__ C,
                        int Nc, int K, int act)
{
    __shared__ GemmTcSmem sm;
    gemm_tile_tc(A, B, bias, C, Nc, K, act, blockIdx.y * 64, blockIdx.x * 64, sm);
}

__global__ void qkv_gemm_tc(const float* __restrict__ A,
                            const float* __restrict__ Wq, const float* __restrict__ bq,
                            const float* __restrict__ Wk, const float* __restrict__ bk,
                            const float* __restrict__ Wv, const float* __restrict__ bv,
                            float* __restrict__ q, float* __restrict__ k, float* __restrict__ v)
{
    __shared__ GemmTcSmem sm;
    const float* B; const float* bias; float* C;
    if (blockIdx.z == 0)      { B = Wq; bias = bq; C = q; }
    else if (blockIdx.z == 1) { B = Wk; bias = bk; C = k; }
    else                      { B = Wv; bias = bv; C = v; }
    gemm_tile_tc(A, B, bias, C, D, D, 0, blockIdx.y * 64, blockIdx.x * 64, sm);
}

// ======= fused GEMM + residual + LayerNorm: C = LN(hin + A@B + bias) =======
// Tile 32 rows x 128 cols (full D) -> grid = N/32 = 128 CTAs.
struct GemmLnSmem {
    u32 As[32 * GSTR];
    u32 Bs[128 * GSTR];
    float ps[32 * 4];
    float pq[32 * 4];
};

__global__ void gemm_ln_tc(const float* __restrict__ A, const float* __restrict__ B,
                           const float* __restrict__ bias, const float* __restrict__ hin,
                           const float* __restrict__ lng, const float* __restrict__ lnb,
                           float* __restrict__ C, int K)
{
    __shared__ GemmLnSmem sm;
    int tid = threadIdx.x;
    int wid = tid >> 5, lane = tid & 31;
    int gq = lane >> 2, tig = lane & 3;
    int wm = wid & 1, wn = wid >> 1;     // 2 x 4
    int r0 = wm * 16, n0 = wn * 32;
    int row0 = blockIdx.x * 32;

    float areg[4], breg[16];
    #pragma unroll
    for (int i = 0; i < 4; i++) {
        int idx = tid + i * 256;
        int am = idx >> 5, ak = idx & 31;
        areg[i] = A[(size_t)(row0 + am) * K + ak];
    }
    #pragma unroll
    for (int i = 0; i < 16; i++) {
        int idx = tid + i * 256;
        int bk = idx >> 7, bn = idx & 127;
        breg[i] = B[(size_t)bk * D + bn];
    }

    float acc[4][4] = {};
    for (int k0 = 0; k0 < K; k0 += 32) {
        __syncthreads();
        #pragma unroll
        for (int i = 0; i < 4; i++) {
            int idx = tid + i * 256;
            int am = idx >> 5, ak = idx & 31;
            sm.As[am * GSTR + ak] = f2tf32(areg[i]);
        }
        #pragma unroll
        for (int i = 0; i < 16; i++) {
            int idx = tid + i * 256;
            int bk = idx >> 7, bn = idx & 127;
            sm.Bs[bn * GSTR + bk] = f2tf32(breg[i]);
        }
        __syncthreads();
        if (k0 + 32 < K) {
            #pragma unroll
            for (int i = 0; i < 4; i++) {
                int idx = tid + i * 256;
                int am = idx >> 5, ak = idx & 31;
                areg[i] = A[(size_t)(row0 + am) * K + (k0 + 32) + ak];
            }
            #pragma unroll
            for (int i = 0; i < 16; i++) {
                int idx = tid + i * 256;
                int bk = idx >> 7, bn = idx & 127;
                breg[i] = B[(size_t)(k0 + 32 + bk) * D + bn];
            }
        }
        #pragma unroll
        for (int ks = 0; ks < 4; ks++) {
            int kk = ks * 8;
            u32 a0 = sm.As[(r0 + gq) * GSTR + kk + tig];
            u32 a1 = sm.As[(r0 + gq + 8) * GSTR + kk + tig];
            u32 a2 = sm.As[(r0 + gq) * GSTR + kk + tig + 4];
            u32 a3 = sm.As[(r0 + gq + 8) * GSTR + kk + tig + 4];
            #pragma unroll
            for (int nt = 0; nt < 4; nt++) {
                int n = n0 + nt * 8;
                u32 b0 = sm.Bs[(n + gq) * GSTR + kk + tig];
                u32 b1 = sm.Bs[(n + gq) * GSTR + kk + tig + 4];
                mma_tf32(acc[nt][0], acc[nt][1], acc[nt][2], acc[nt][3],
                         a0, a1, a2, a3, b0, b1);
            }
        }
    }

    int ra = row0 + r0 + gq, rb = ra + 8;
    float va[4][2], vb[4][2];
    float sa = 0.0f, qa = 0.0f, sb = 0.0f, qb = 0.0f;
    #pragma unroll
    for (int nt = 0; nt < 4; nt++) {
        int c = n0 + nt * 8 + 2 * tig;
        float2 bc  = *(const float2*)&bias[c];
        float2 ha  = *(const float2*)&hin[(size_t)ra * D + c];
        float2 hb  = *(const float2*)&hin[(size_t)rb * D + c];
        va[nt][0] = acc[nt][0] + bc.x + ha.x;
        va[nt][1] = acc[nt][1] + bc.y + ha.y;
        vb[nt][0] = acc[nt][2] + bc.x + hb.x;
        vb[nt][1] = acc[nt][3] + bc.y + hb.y;
        sa += va[nt][0] + va[nt][1];
        qa += va[nt][0] * va[nt][0] + va[nt][1] * va[nt][1];
        sb += vb[nt][0] + vb[nt][1];
        qb += vb[nt][0] * vb[nt][0] + vb[nt][1] * vb[nt][1];
    }
    #pragma unroll
    for (int off = 1; off <= 2; off <<= 1) {
        sa += __shfl_xor_sync(0xffffffffu, sa, off);
        qa += __shfl_xor_sync(0xffffffffu, qa, off);
        sb += __shfl_xor_sync(0xffffffffu, sb, off);
        qb += __shfl_xor_sync(0xffffffffu, qb, off);
    }
    if (tig == 0) {
        sm.ps[(r0 + gq) * 4 + wn] = sa;     sm.pq[(r0 + gq) * 4 + wn] = qa;
        sm.ps[(r0 + gq + 8) * 4 + wn] = sb; sm.pq[(r0 + gq + 8) * 4 + wn] = qb;
    }
    __syncthreads();
    int ia4 = (r0 + gq) * 4, ib4 = (r0 + gq + 8) * 4;
    float Sa = sm.ps[ia4] + sm.ps[ia4 + 1] + sm.ps[ia4 + 2] + sm.ps[ia4 + 3];
    float Qa = sm.pq[ia4] + sm.pq[ia4 + 1] + sm.pq[ia4 + 2] + sm.pq[ia4 + 3];
    float Sb = sm.ps[ib4] + sm.ps[ib4 + 1] + sm.ps[ib4 + 2] + sm.ps[ib4 + 3];
    float Qb = sm.pq[ib4] + sm.pq[ib4 + 1] + sm.pq[ib4 + 2] + sm.pq[ib4 + 3];
    float ma = Sa * (1.0f / D), vva = Qa * (1.0f / D) - ma * ma;
    float mb = Sb * (1.0f / D), vvb = Qb * (1.0f / D) - mb * mb;
    float ia = rsqrtf(vva + EPS), ib = rsqrtf(vvb + EPS);
    #pragma unroll
    for (int nt = 0; nt < 4; nt++) {
        int c = n0 + nt * 8 + 2 * tig;
        float2 gg = *(const float2*)&lng[c];
        float2 bb = *(const float2*)&lnb[c];
        *(float2*)&C[(size_t)ra * D + c] =
            make_float2((va[nt][0] - ma) * ia * gg.x + bb.x,
                        (va[nt][1] - ma) * ia * gg.y + bb.y);
        *(float2*)&C[(size_t)rb * D + c] =
            make_float2((vb[nt][0] - mb) * ib * gg.x + bb.x,
                        (vb[nt][1] - mb) * ib * gg.y + bb.y);
    }
}

// ======= flash attention, tf32 MMA, no-max softmax, raw-bit tf32 stores =======
// V tile stored with xor-swizzle (col ^ ((row>>3)&3)) -> conflict-free stores AND loads.
#define TSTR 68
__global__ void flash_attn_tc(const float* __restrict__ q, const float* __restrict__ k,
                              const float* __restrict__ v, float* __restrict__ o)
{
    extern __shared__ float fsm[];
    // regions of 64*TSTR floats: 0=Qs, 1=Ks0, 2=Ks1, 3=Vs0, 4=Vs1, 5=Ps
    float* Qs = fsm;
    u32*   PsU = (u32*)(fsm + 5 * 64 * TSTR);
    float* l_part = fsm + 6 * 64 * TSTR;   // [64][2]
    u32* QsU = (u32*)Qs;

    int tid  = threadIdx.x;
    int wid  = tid >> 5, lane = tid & 31;
    int g    = lane >> 2, tig = lane & 3;
    int wm   = wid & 3, wn = wid >> 2;
    int r0   = wm * 16, n0 = wn * 32;
    int qrow0 = blockIdx.x * 64;
    int hcol  = blockIdx.y * DH;

    #pragma unroll
    for (int i = 0; i < 16; i++) {
        int idx = tid + i * 256;
        int r = idx >> 6, d = idx & 63;
        QsU[r * TSTR + d] = f2tf32(q[(size_t)(qrow0 + r) * D + hcol + d]);
    }

    float kreg[16], vreg[16];
    #pragma unroll
    for (int i = 0; i < 16; i++) {
        int idx = tid + i * 256;
        int c = idx >> 6, d = idx & 63;
        kreg[i] = k[(size_t)c * D + hcol + d];
        vreg[i] = v[(size_t)c * D + hcol + d];
    }
    __syncthreads();

    // hoist Q fragments (loop-invariant)
    u32 qa[8][4];
    #pragma unroll
    for (int ks = 0; ks < 8; ks++) {
        int k0 = ks * 8;
        qa[ks][0] = QsU[(r0 + g) * TSTR + k0 + tig];
        qa[ks][1] = QsU[(r0 + g + 8) * TSTR + k0 + tig];
        qa[ks][2] = QsU[(r0 + g) * TSTR + k0 + tig + 4];
        qa[ks][3] = QsU[(r0 + g + 8) * TSTR + k0 + tig + 4];
    }

    const float scale = 0.125f;
    float la = 0.0f, lb = 0.0f;
    float of[4][4] = {};
    int p = 0;

    for (int kb = 0; kb < N; kb += 64) {
        u32* KsU = (u32*)(fsm + (1 + p) * 64 * TSTR);
        u32* VsU = (u32*)(fsm + (3 + p) * 64 * TSTR);
        #pragma unroll
        for (int i = 0; i < 16; i++) {
            int idx = tid + i * 256;
            int c = idx >> 6, d = idx & 63;
            KsU[c * TSTR + d] = __float_as_uint(kreg[i]);           // raw fp32 = tf32 truncate
            VsU[d * TSTR + (c ^ ((d >> 3) & 3))] = __float_as_uint(vreg[i]);  // swizzled, conflict-free
        }
        __syncthreads();                       // barrier A
        if (kb + 64 < N) {
            #pragma unroll
            for (int i = 0; i < 16; i++) {
                int idx = tid + i * 256;
                int c = idx >> 6, d = idx & 63;
                kreg[i] = k[(size_t)(kb + 64 + c) * D + hcol + d];
                vreg[i] = v[(size_t)(kb + 64 + c) * D + hcol + d];
            }
        }

        // S = Q @ K^T, exp in-register, store P (raw bits), accumulate l
        {
            float sf[4][4] = {};
            #pragma unroll
            for (int ks = 0; ks < 8; ks++) {
                int k0 = ks * 8;
                #pragma unroll
                for (int nt = 0; nt < 4; nt++) {
                    int n = n0 + nt * 8;
                    u32 b0 = KsU[(n + g) * TSTR + k0 + tig];
                    u32 b1 = KsU[(n + g) * TSTR + k0 + tig + 4];
                    mma_tf32(sf[nt][0], sf[nt][1], sf[nt][2], sf[nt][3],
                             qa[ks][0], qa[ks][1], qa[ks][2], qa[ks][3], b0, b1);
                }
            }
            #pragma unroll
            for (int nt = 0; nt < 4; nt++) {
                float p0 = __expf(sf[nt][0] * scale);
                float p1 = __expf(sf[nt][1] * scale);
                float p2 = __expf(sf[nt][2] * scale);
                float p3 = __expf(sf[nt][3] * scale);
                la += p0 + p1;
                lb += p2 + p3;
                int n = n0 + nt * 8 + 2 * tig;
                *(uint2*)&PsU[(r0 + g) * TSTR + n] =
                    make_uint2(__float_as_uint(p0), __float_as_uint(p1));
                *(uint2*)&PsU[(r0 + g + 8) * TSTR + n] =
                    make_uint2(__float_as_uint(p2), __float_as_uint(p3));
            }
        }
        __syncthreads();                       // barrier B

        // O += P @ V  (V fragment cols xor-swizzled; xor uniform per nt)
        #pragma unroll
        for (int ks = 0; ks < 8; ks++) {
            int k0 = ks * 8;
            u32 a0 = PsU[(r0 + g) * TSTR + k0 + tig];
            u32 a1 = PsU[(r0 + g + 8) * TSTR + k0 + tig];
            u32 a2 = PsU[(r0 + g) * TSTR + k0 + tig + 4];
            u32 a3 = PsU[(r0 + g + 8) * TSTR + k0 + tig + 4];
            #pragma unroll
            for (int nt = 0; nt < 4; nt++) {
                int n = n0 + nt * 8;
                int x4 = ((n0 >> 3) + nt) & 3;
                int tigx = tig ^ x4;
                u32 b0 = VsU[(n + g) * TSTR + k0 + tigx];
                u32 b1 = VsU[(n + g) * TSTR + k0 + tigx + 4];
                mma_tf32(of[nt][0], of[nt][1], of[nt][2], of[nt][3],
                         a0, a1, a2, a3, b0, b1);
            }
        }
        p ^= 1;
    }

    // reduce l over quad, then across the 2 n-warps via smem
    la += __shfl_xor_sync(0xffffffffu, la, 1);
    la += __shfl_xor_sync(0xffffffffu, la, 2);
    lb += __shfl_xor_sync(0xffffffffu, lb, 1);
    lb += __shfl_xor_sync(0xffffffffu, lb, 2);
    __syncthreads();
    if (tig == 0) {
        l_part[(r0 + g) * 2 + wn]     = la;
        l_part[(r0 + g + 8) * 2 + wn] = lb;
    }
    __syncthreads();
    float linv  = 1.0f / (l_part[(r0 + g) * 2]     + l_part[(r0 + g) * 2 + 1]);
    float linv8 = 1.0f / (l_part[(r0 + g + 8) * 2] + l_part[(r0 + g + 8) * 2 + 1]);
    #pragma unroll
    for (int nt = 0; nt < 4; nt++) {
        int n = hcol + n0 + nt * 8 + 2 * tig;
        int ra = qrow0 + r0 + g, rb = qrow0 + r0 + g + 8;
        *(float2*)&o[(size_t)ra * D + n] = make_float2(of[nt][0] * linv,  of[nt][1] * linv);
        *(float2*)&o[(size_t)rb * D + n] = make_float2(of[nt][2] * linv8, of[nt][3] * linv8);
    }
}

// ======= hypergraph conv via CSR build + gather (no float atomics) =======
__device__ void block_scan_excl(const int* cnt, int* start, int* cur, int n, int* smbuf)
{
    int tid = threadIdx.x;               // 1024 threads
    int per = n >> 10;
    int base = tid * per;
    int vals[4];
    int local = 0;
    for (int i = 0; i < per; i++) { vals[i] = cnt[base + i]; local += vals[i]; }
    int lane = tid & 31, warp = tid >> 5;
    int x = local;
    #pragma unroll
    for (int off = 1; off < 32; off <<= 1) {
        int y = __shfl_up_sync(0xffffffffu, x, off);
        if (lane >= off) x += y;
    }
    if (lane == 31) smbuf[warp] = x;
    __syncthreads();
    if (warp == 0) {
        int w = smbuf[lane];
        #pragma unroll
        for (int off = 1; off < 32; off <<= 1) {
            int y = __shfl_up_sync(0xffffffffu, w, off);
            if (lane >= off) w += y;
        }
        smbuf[lane] = w;
    }
    __syncthreads();
    int excl = ((warp > 0) ? smbuf[warp - 1] : 0) + x - local;
    for (int i = 0; i < per; i++) {
        start[base + i] = excl;
        cur[base + i]   = excl;
        excl += vals[i];
    }
    __syncthreads();
}

// fused zero + count (smem histograms) + scan + publish: ONE CTA, 1024 threads
__global__ void build_csr_kernel(const void* __restrict__ edge)
{
    __shared__ int sce[NE];
    __shared__ int scn[N];
    __shared__ int smbuf[32];
    int tid = threadIdx.x;
    for (int i = tid; i < NE; i += 1024) sce[i] = 0;
    for (int i = tid; i < N;  i += 1024) scn[i] = 0;
    __syncthreads();
    for (int i = tid; i < NNZ; i += 1024) {
        int2 ne = load_edge(edge, i);
        if ((unsigned)ne.x < N && (unsigned)ne.y < NE) {
            atomicAdd(&scn[ne.x], 1);
            atomicAdd(&sce[ne.y], 1);
        }
    }
    __syncthreads();
    block_scan_excl(sce, g_start_e, g_cur_e, NE, smbuf);
    block_scan_excl(scn, g_start_n, g_cur_n, N, smbuf);
    for (int i = tid; i < NE; i += 1024) g_cnt_e[i] = sce[i];
    for (int i = tid; i < N;  i += 1024) g_cnt_n[i] = scn[i];
}

__global__ void fill_kernel(const void* __restrict__ edge)
{
    int i = blockIdx.x * blockDim.x + threadIdx.x;
    if (i < NNZ) {
        int2 ne = load_edge(edge, i);
        if ((unsigned)ne.x < N && (unsigned)ne.y < NE) {
            int pe = atomicAdd(&g_cur_e[ne.y], 1);
            g_bucket_e[pe] = ne.x;
            int pn = atomicAdd(&g_cur_n[ne.x], 1);
            g_bucket_n[pn] = ne.y;
        }
    }
}

__global__ void gather_e_kernel(const float* __restrict__ xt, float* __restrict__ e)
{
    int he = blockIdx.x;                 // NE blocks, 128 threads
    int tid = threadIdx.x;
    int s = g_start_e[he], dg = g_cnt_e[he];
    float acc = 0.0f;
    int j = 0;
    for (; j + 4 <= dg; j += 4) {
        int n0 = g_bucket_e[s + j], n1 = g_bucket_e[s + j + 1];
        int n2 = g_bucket_e[s + j + 2], n3 = g_bucket_e[s + j + 3];
        acc += xt[(size_t)n0 * D + tid] + xt[(size_t)n1 * D + tid]
             + xt[(size_t)n2 * D + tid] + xt[(size_t)n3 * D + tid];
    }
    for (; j < dg; j++)
        acc += xt[(size_t)g_bucket_e[s + j] * D + tid];
    float bi = (dg > 0) ? (1.0f / dg) : 0.0f;
    e[(size_t)he * D + tid] = acc * bi;
}

__global__ void gather_out_kernel(const float* __restrict__ e, const float* __restrict__ bh,
                                  float* __restrict__ out)
{
    int nd = blockIdx.x;                 // N blocks, 128 threads
    int tid = threadIdx.x;
    int s = g_start_n[nd], dg = g_cnt_n[nd];
    float acc = 0.0f;
    int j = 0;
    for (; j + 4 <= dg; j += 4) {
        int h0 = g_bucket_n[s + j], h1 = g_bucket_n[s + j + 1];
        int h2 = g_bucket_n[s + j + 2], h3 = g_bucket_n[s + j + 3];
        acc += e[(size_t)h0 * D + tid] + e[(size_t)h1 * D + tid]
             + e[(size_t)h2 * D + tid] + e[(size_t)h3 * D + tid];
    }
    for (; j < dg; j++)
        acc += e[(size_t)g_bucket_n[s + j] * D + tid];
    float di = (dg > 0) ? (1.0f / dg) : 0.0f;
    out[(size_t)nd * D + tid] = fmaxf(acc * di + bh[tid], 0.0f);
}

// ---------------- launch ----------------
extern "C" void kernel_launch(void* const* d_in, const int* in_sizes, int n_in,
                              void* d_out, int out_size)
{
    const float* x    = (const float*)d_in[0];
    const void*  edge = d_in[1];
    const float* Wq = (const float*)d_in[2],  *bq  = (const float*)d_in[3];
    const float* Wk = (const float*)d_in[4],  *bk  = (const float*)d_in[5];
    const float* Wv = (const float*)d_in[6],  *bv  = (const float*)d_in[7];
    const float* Wo = (const float*)d_in[8],  *bo  = (const float*)d_in[9];
    const float* g1 = (const float*)d_in[10], *b1  = (const float*)d_in[11];
    const float* W1 = (const float*)d_in[12], *bf1 = (const float*)d_in[13];
    const float* W2 = (const float*)d_in[14], *bf2 = (const float*)d_in[15];
    const float* g2 = (const float*)d_in[16], *b2  = (const float*)d_in[17];
    const float* Wh = (const float*)d_in[18], *bh  = (const float*)d_in[19];
    float* out = (float*)d_out;

    float *h, *q, *k, *v, *o, *z, *e;
    cudaGetSymbolAddress((void**)&h, g_h);
    cudaGetSymbolAddress((void**)&q, g_q);
    cudaGetSymbolAddress((void**)&k, g_k);
    cudaGetSymbolAddress((void**)&v, g_v);
    cudaGetSymbolAddress((void**)&o, g_o);
    cudaGetSymbolAddress((void**)&z, g_z);
    cudaGetSymbolAddress((void**)&e, g_e);

    const int FSMEM = (6 * 64 * TSTR + 128) * (int)sizeof(float);  // ~105 KB
    cudaFuncSetAttribute(flash_attn_tc, cudaFuncAttributeMaxDynamicSharedMemorySize, FSMEM);

    detect_edge_kernel<<<1, 32>>>((const int*)edge);

    // CSR build: fused single-CTA count+scan, then full-grid fill
    build_csr_kernel<<<1, 1024>>>(edge);
    fill_kernel<<<NNZ / 256, 256>>>(edge);

    dim3 gD(D / 64, N / 64);       // 2 x 64
    dim3 gF(FF / 64, N / 64);      // 4 x 64
    dim3 gQKV(D / 64, N / 64, 3);  // 2 x 64 x 3

    for (int it = 0; it < 2; ++it) {
        const float* hin = (it == 0) ? x : h;
        qkv_gemm_tc<<<gQKV, 256>>>(hin, Wq, bq, Wk, bk, Wv, bv, q, k, v);
        flash_attn_tc<<<dim3(N / 64, H), 256, FSMEM>>>(q, k, v, o);
        gemm_ln_tc<<<N / 32, 256>>>(o, Wo, bo, hin, g1, b1, h, D);
        gemm_tc<<<gF, 256>>>(h, W1, bf1, z, FF, D, 1);
        gemm_ln_tc<<<N / 32, 256>>>(z, W2, bf2, h, g2, b2, h, FF);
    }

    // xt = h @ Wh (reuse q buffer)
    gemm_tc<<<gD, 256>>>(h, Wh, nullptr, q, D, D, 0);

    gather_e_kernel<<<NE, 128>>>(q, e);
    gather_out_kernel<<<N, 128>>>(e, bh, out);
}